// round 4
// baseline (speedup 1.0000x reference)
#include <cuda_runtime.h>
#include <cstdint>

#define NPTS 500000
#define NT 7813
#define EWB 31250
#define NC0 4096
#define NC1 32768
#define NC2 131072
#define SEG1 NC0
#define SEG2 (NC0+NC1)
#define SEGT (NC0+NC1+NC2)

__device__ float g_Y[(size_t)NPTS*448];
__device__ float g_pw[(size_t)NPTS*64];
__device__ float g_cat[(size_t)NPTS*128];
__device__ float g_z[(size_t)NPTS*64];
__device__ float g_fused[(size_t)NPTS*64];
__device__ float g_h1[(size_t)NPTS*64];
__device__ float g_h2[(size_t)NPTS*64];
__device__ float g_segTmp[(size_t)NC2*64];
__device__ float g_segP[(size_t)SEGT*64];
__device__ float g_cnt[SEGT];
__device__ float g_colsum[640];
__device__ float g_colsq[640];
__device__ float g_bnScale[640];
__device__ float g_bnShift[640];
__device__ unsigned g_maxbits[3];

__device__ __forceinline__ unsigned fenc(float f){
    unsigned u=__float_as_uint(f);
    return (u&0x80000000u)? ~u : (u|0x80000000u);
}
__device__ __forceinline__ float fdec(unsigned v){
    unsigned u=(v&0x80000000u)? (v^0x80000000u) : ~v;
    return __uint_as_float(u);
}
__device__ __forceinline__ void fma16(float acc[4][4], float4 a, float4 b){
    acc[0][0]=fmaf(a.x,b.x,acc[0][0]); acc[0][1]=fmaf(a.x,b.y,acc[0][1]);
    acc[0][2]=fmaf(a.x,b.z,acc[0][2]); acc[0][3]=fmaf(a.x,b.w,acc[0][3]);
    acc[1][0]=fmaf(a.y,b.x,acc[1][0]); acc[1][1]=fmaf(a.y,b.y,acc[1][1]);
    acc[1][2]=fmaf(a.y,b.z,acc[1][2]); acc[1][3]=fmaf(a.y,b.w,acc[1][3]);
    acc[2][0]=fmaf(a.z,b.x,acc[2][0]); acc[2][1]=fmaf(a.z,b.y,acc[2][1]);
    acc[2][2]=fmaf(a.z,b.z,acc[2][2]); acc[2][3]=fmaf(a.z,b.w,acc[2][3]);
    acc[3][0]=fmaf(a.w,b.x,acc[3][0]); acc[3][1]=fmaf(a.w,b.y,acc[3][1]);
    acc[3][2]=fmaf(a.w,b.z,acc[3][2]); acc[3][3]=fmaf(a.w,b.w,acc[3][3]);
}
__device__ __forceinline__ float4 bnrelu4(float4 y, float4 sc, float4 sh){
    float4 o;
    o.x=fmaxf(fmaf(y.x,sc.x,sh.x),0.f); o.y=fmaxf(fmaf(y.y,sc.y,sh.y),0.f);
    o.z=fmaxf(fmaf(y.z,sc.z,sh.z),0.f); o.w=fmaxf(fmaf(y.w,sc.w,sh.w),0.f);
    return o;
}
__device__ __forceinline__ void storeT(float* At, int j, int p, float4 a){
    At[(j+0)*68+p]=a.x; At[(j+1)*68+p]=a.y; At[(j+2)*68+p]=a.z; At[(j+3)*68+p]=a.w;
}

__global__ void k_zero_init(){
    size_t i=(size_t)blockIdx.x*blockDim.x+threadIdx.x;
    size_t stride=(size_t)gridDim.x*blockDim.x;
    for(size_t j=i;j<(size_t)SEGT*64;j+=stride) g_segP[j]=0.f;
    if(i<SEGT) g_cnt[i]=0.f;
    if(i<640){ g_colsum[i]=0.f; g_colsq[i]=0.f; }
    if(i<3) g_maxbits[i]=0u;
}
__global__ void k_zero_segtmp(size_t n){
    size_t i=(size_t)blockIdx.x*blockDim.x+threadIdx.x;
    size_t stride=(size_t)gridDim.x*blockDim.x;
    for(size_t j=i;j<n;j+=stride) g_segTmp[j]=0.f;
}
__global__ void k_counts(const int* __restrict__ c0, const int* __restrict__ c1,
                         const int* __restrict__ c2){
    int n=blockIdx.x*blockDim.x+threadIdx.x;
    if(n<NPTS){
        atomicAdd(&g_cnt[c0[n]],1.f);
        atomicAdd(&g_cnt[SEG1+c1[n]],1.f);
        atomicAdd(&g_cnt[SEG2+c2[n]],1.f);
    }
}

// feat @ [W_lw0..2 | W_proj0..3], BN-stats epilogue
__global__ void k_gemm_all(const float* __restrict__ feat, const float* __restrict__ Wlw,
                           const float* __restrict__ Wproj){
    __shared__ float At[64*68];
    __shared__ float Bs[64*64];
    __shared__ float redS[16*64];
    __shared__ float redQ[16*64];
    int r0=blockIdx.x*64, tid=threadIdx.x;
    int p=tid>>2, t4=tid&3, r=r0+p;
    int ty=tid>>4, tx=tid&15;
#pragma unroll
    for(int v=0;v<4;v++){
        int j=t4*16+v*4;
        float4 a=(r<NPTS)? *(const float4*)(feat+(size_t)r*64+j) : make_float4(0,0,0,0);
        storeT(At,j,p,a);
    }
    for(int t=0;t<7;t++){
        const float* W=(t<3)? (Wlw+t*4096) : (Wproj+(t-3)*4096);
        __syncthreads();
        for(int li=tid;li<1024;li+=256) ((float4*)Bs)[li]=((const float4*)W)[li];
        __syncthreads();
        float acc[4][4]={};
#pragma unroll 16
        for(int j=0;j<64;j++){
            float4 a=*(float4*)(At+j*68+ty*4);
            float4 b=*(float4*)(Bs+j*64+tx*4);
            fma16(acc,a,b);
        }
#pragma unroll
        for(int u=0;u<4;u++){
            int rr=r0+ty*4+u;
            if(rr<NPTS)
                *(float4*)(g_Y+(size_t)rr*448+t*64+tx*4)=
                    make_float4(acc[u][0],acc[u][1],acc[u][2],acc[u][3]);
        }
        float s[4]={0,0,0,0}, q[4]={0,0,0,0};
#pragma unroll
        for(int u=0;u<4;u++)
#pragma unroll
            for(int cu=0;cu<4;cu++){ float v=acc[u][cu]; s[cu]+=v; q[cu]+=v*v; }
#pragma unroll
        for(int cu=0;cu<4;cu++){ redS[ty*64+tx*4+cu]=s[cu]; redQ[ty*64+tx*4+cu]=q[cu]; }
        __syncthreads();
        if(tid<64){
            float ss=0,qq=0;
#pragma unroll
            for(int y=0;y<16;y++){ ss+=redS[y*64+tid]; qq+=redQ[y*64+tid]; }
            atomicAdd(&g_colsum[t*64+tid],ss);
            atomicAdd(&g_colsq[t*64+tid],qq);
        }
    }
}

__global__ void k_bnparam448(const float* __restrict__ glw, const float* __restrict__ blw,
                             const float* __restrict__ gproj, const float* __restrict__ bproj){
    int c=blockIdx.x*blockDim.x+threadIdx.x;
    if(c>=448) return;
    int grp=c>>6, ch=c&63;
    float g=(grp<3)? glw[grp*64+ch] : gproj[(grp-3)*64+ch];
    float b=(grp<3)? blw[grp*64+ch] : bproj[(grp-3)*64+ch];
    float inv=1.0f/(float)NPTS;
    float mu=g_colsum[c]*inv;
    float var=g_colsq[c]*inv-mu*mu;
    float sc=g*rsqrtf(var+1e-3f);
    g_bnScale[c]=sc; g_bnShift[c]=b-mu*sc;
}
__global__ void k_bnparam64(int off, const float* __restrict__ g, const float* __restrict__ b){
    int c=threadIdx.x;
    if(c>=64) return;
    float inv=1.0f/(float)NPTS;
    float mu=g_colsum[off+c]*inv;
    float var=g_colsq[off+c]*inv-mu*mu;
    float sc=g[c]*rsqrtf(var+1e-3f);
    g_bnScale[off+c]=sc; g_bnShift[off+c]=b[c]-mu*sc;
}

// pw = relu(bn(Y_lw_i)); scatter cluster sums into g_segTmp
__global__ void k_pw_scatter(const int* __restrict__ cl, int ycol, int bnoff){
    size_t i=(size_t)blockIdx.x*blockDim.x+threadIdx.x;
    if(i>=(size_t)NPTS*16) return;
    int n=(int)(i>>4); int c=((int)i&15)*4;
    float4 y=*(const float4*)(g_Y+(size_t)n*448+ycol+c);
    float4 sc=*(const float4*)(g_bnScale+bnoff+c);
    float4 sh=*(const float4*)(g_bnShift+bnoff+c);
    float4 o=bnrelu4(y,sc,sh);
    *(float4*)(g_pw+(size_t)n*64+c)=o;
    float* seg=g_segTmp+(size_t)cl[n]*64+c;
    atomicAdd(seg,o.x); atomicAdd(seg+1,o.y); atomicAdd(seg+2,o.z); atomicAdd(seg+3,o.w);
}

// pw = (pw - mean[cl]) @ W_w (in place) + global-max reduction
__global__ void k_meansub_gemm(const int* __restrict__ cl, const float* __restrict__ Ww,
                               int cntOff, int maxIdx){
    __shared__ float At[64*68];
    __shared__ float Bs[64*64];
    __shared__ float wmax[8];
    int r0=blockIdx.x*64, tid=threadIdx.x;
    int p=tid>>2, t4=tid&3, r=r0+p;
    {
        int s=0; float inv=0.f;
        if(r<NPTS){ s=cl[r]; inv=1.f/fmaxf(g_cnt[cntOff+s],1.f); }
#pragma unroll
        for(int v=0;v<4;v++){
            int j=t4*16+v*4;
            float4 a=make_float4(0,0,0,0);
            if(r<NPTS){
                float4 pw=*(const float4*)(g_pw+(size_t)r*64+j);
                float4 m=*(const float4*)(g_segTmp+(size_t)s*64+j);
                a.x=pw.x-m.x*inv; a.y=pw.y-m.y*inv; a.z=pw.z-m.z*inv; a.w=pw.w-m.w*inv;
            }
            storeT(At,j,p,a);
        }
    }
    for(int li=tid;li<1024;li+=256) ((float4*)Bs)[li]=((const float4*)Ww)[li];
    __syncthreads();
    int ty=tid>>4, tx=tid&15;
    float acc[4][4]={};
#pragma unroll 16
    for(int j=0;j<64;j++){
        float4 a=*(float4*)(At+j*68+ty*4);
        float4 b=*(float4*)(Bs+j*64+tx*4);
        fma16(acc,a,b);
    }
    float m=-3.0e38f;
#pragma unroll
    for(int u=0;u<4;u++){
        int rr=r0+ty*4+u;
        if(rr<NPTS){
            *(float4*)(g_pw+(size_t)rr*64+tx*4)=
                make_float4(acc[u][0],acc[u][1],acc[u][2],acc[u][3]);
            m=fmaxf(m,fmaxf(fmaxf(acc[u][0],acc[u][1]),fmaxf(acc[u][2],acc[u][3])));
        }
    }
#pragma unroll
    for(int o=16;o>0;o>>=1) m=fmaxf(m,__shfl_down_sync(0xffffffffu,m,o));
    if((tid&31)==0) wmax[tid>>5]=m;
    __syncthreads();
    if(tid==0){
        float mm=wmax[0];
#pragma unroll
        for(int w=1;w<8;w++) mm=fmaxf(mm,wmax[w]);
        atomicMax(&g_maxbits[maxIdx],fenc(mm));
    }
}

// pw = exp(pw - gmax); scatter denom sums
__global__ void k_exp_scatter(const int* __restrict__ cl, int maxIdx){
    size_t i=(size_t)blockIdx.x*blockDim.x+threadIdx.x;
    if(i>=(size_t)NPTS*16) return;
    int n=(int)(i>>4); int c=((int)i&15)*4;
    float gmax=fdec(g_maxbits[maxIdx]);
    float4 v=*(float4*)(g_pw+(size_t)n*64+c);
    v.x=__expf(v.x-gmax); v.y=__expf(v.y-gmax); v.z=__expf(v.z-gmax); v.w=__expf(v.w-gmax);
    *(float4*)(g_pw+(size_t)n*64+c)=v;
    float* seg=g_segTmp+(size_t)cl[n]*64+c;
    atomicAdd(seg,v.x); atomicAdd(seg+1,v.y); atomicAdd(seg+2,v.z); atomicAdd(seg+3,v.w);
}

// pfeat = relu(bn(Y_proj_i)) * pw/(denom+1e-6); scatter into g_segP
__global__ void k_pfeat_scatter(const int* __restrict__ cl, int ycol, int bnoff, size_t segOff){
    size_t i=(size_t)blockIdx.x*blockDim.x+threadIdx.x;
    if(i>=(size_t)NPTS*16) return;
    int n=(int)(i>>4); int c=((int)i&15)*4;
    float4 y=*(const float4*)(g_Y+(size_t)n*448+ycol+c);
    float4 sc=*(const float4*)(g_bnScale+bnoff+c);
    float4 sh=*(const float4*)(g_bnShift+bnoff+c);
    float4 o=bnrelu4(y,sc,sh);
    float4 e=*(const float4*)(g_pw+(size_t)n*64+c);
    int s=cl[n];
    float4 d=*(const float4*)(g_segTmp+(size_t)s*64+c);
    float4 val;
    val.x=o.x*e.x/(d.x+1e-6f); val.y=o.y*e.y/(d.y+1e-6f);
    val.z=o.z*e.z/(d.z+1e-6f); val.w=o.w*e.w/(d.w+1e-6f);
    float* seg=g_segP+segOff+(size_t)s*64+c;
    atomicAdd(seg,val.x); atomicAdd(seg+1,val.y); atomicAdd(seg+2,val.z); atomicAdd(seg+3,val.w);
}

// adp softmax + 3-scale mix; write [f_last | mix] into g_cat (N x 128)
__global__ void k_mix(const float* __restrict__ feat, const int* __restrict__ c0,
                      const int* __restrict__ c1, const int* __restrict__ c2,
                      const float* __restrict__ Wadp){
    __shared__ float ft[64*68];
    __shared__ float wa[192];
    __shared__ float adp[64*3];
    int r0=blockIdx.x*64, tid=threadIdx.x;
    int p=tid>>2, t4=tid&3, r=r0+p;
    if(tid<192) wa[tid]=Wadp[tid];
#pragma unroll
    for(int v=0;v<4;v++){
        int j=t4*16+v*4;
        float4 a=(r<NPTS)? *(const float4*)(feat+(size_t)r*64+j) : make_float4(0,0,0,0);
        *(float4*)(ft+p*68+j)=a;
    }
    __syncthreads();
    if(tid<64){
        float l0=0,l1=0,l2=0;
#pragma unroll 16
        for(int j=0;j<64;j++){
            float f=ft[tid*68+j];
            l0=fmaf(f,wa[j*3],l0); l1=fmaf(f,wa[j*3+1],l1); l2=fmaf(f,wa[j*3+2],l2);
        }
        float mx=fmaxf(l0,fmaxf(l1,l2));
        float e0=__expf(l0-mx), e1=__expf(l1-mx), e2=__expf(l2-mx);
        float inv=1.f/(e0+e1+e2);
        adp[tid*3]=e0*inv; adp[tid*3+1]=e1*inv; adp[tid*3+2]=e2*inv;
    }
    __syncthreads();
    if(r>=NPTS) return;
    float w0=adp[p*3], w1=adp[p*3+1], w2=adp[p*3+2];
    size_t b0=(size_t)c0[r]*64;
    size_t b1=(size_t)(SEG1+c1[r])*64;
    size_t b2=(size_t)(SEG2+c2[r])*64;
#pragma unroll
    for(int v=0;v<4;v++){
        int c=t4*16+v*4;
        float4 y=*(const float4*)(g_Y+(size_t)r*448+384+c);
        float4 sc=*(const float4*)(g_bnScale+384+c);
        float4 sh=*(const float4*)(g_bnShift+384+c);
        float4 fl=bnrelu4(y,sc,sh);
        float4 a0=*(const float4*)(g_segP+b0+c);
        float4 a1=*(const float4*)(g_segP+b1+c);
        float4 a2=*(const float4*)(g_segP+b2+c);
        float4 m;
        m.x=w0*a0.x+w1*a1.x+w2*a2.x; m.y=w0*a0.y+w1*a1.y+w2*a2.y;
        m.z=w0*a0.z+w1*a1.z+w2*a2.z; m.w=w0*a0.w+w1*a1.w+w2*a2.w;
        *(float4*)(g_cat+(size_t)r*128+c)=fl;
        *(float4*)(g_cat+(size_t)r*128+64+c)=m;
    }
}

// z = g_cat (N x 128) @ W_fuse (128 x 64), BN-stats epilogue (offset 448)
__global__ void k_gemm128(const float* __restrict__ Wfuse){
    __shared__ float At[64*68];
    __shared__ float Bs[64*64];
    int r0=blockIdx.x*64, tid=threadIdx.x;
    int p=tid>>2, t4=tid&3, r=r0+p;
    int ty=tid>>4, tx=tid&15;
    float acc[4][4]={};
    for(int kc=0;kc<2;kc++){
        __syncthreads();
#pragma unroll
        for(int v=0;v<4;v++){
            int j=t4*16+v*4;
            float4 a=(r<NPTS)? *(const float4*)(g_cat+(size_t)r*128+kc*64+j)
                             : make_float4(0,0,0,0);
            storeT(At,j,p,a);
        }
        for(int li=tid;li<1024;li+=256) ((float4*)Bs)[li]=((const float4*)(Wfuse+kc*4096))[li];
        __syncthreads();
#pragma unroll 16
        for(int j=0;j<64;j++){
            float4 a=*(float4*)(At+j*68+ty*4);
            float4 b=*(float4*)(Bs+j*64+tx*4);
            fma16(acc,a,b);
        }
    }
#pragma unroll
    for(int u=0;u<4;u++){
        int rr=r0+ty*4+u;
        if(rr<NPTS)
            *(float4*)(g_z+(size_t)rr*64+tx*4)=
                make_float4(acc[u][0],acc[u][1],acc[u][2],acc[u][3]);
    }
    __syncthreads();
    float* redS=At; float* redQ=At+1024;
    float s[4]={0,0,0,0}, q[4]={0,0,0,0};
#pragma unroll
    for(int u=0;u<4;u++)
#pragma unroll
        for(int cu=0;cu<4;cu++){ float v=acc[u][cu]; s[cu]+=v; q[cu]+=v*v; }
#pragma unroll
    for(int cu=0;cu<4;cu++){ redS[ty*64+tx*4+cu]=s[cu]; redQ[ty*64+tx*4+cu]=q[cu]; }
    __syncthreads();
    if(tid<64){
        float ss=0,qq=0;
#pragma unroll
        for(int y=0;y<16;y++){ ss+=redS[y*64+tid]; qq+=redQ[y*64+tid]; }
        atomicAdd(&g_colsum[448+tid],ss);
        atomicAdd(&g_colsq[448+tid],qq);
    }
}

__global__ void k_applyfuse(const float* __restrict__ feat){
    size_t i=(size_t)blockIdx.x*blockDim.x+threadIdx.x;
    if(i>=(size_t)NPTS*16) return;
    int n=(int)(i>>4); int c=((int)i&15)*4;
    float4 z=*(const float4*)(g_z+(size_t)n*64+c);
    float4 sc=*(const float4*)(g_bnScale+448+c);
    float4 sh=*(const float4*)(g_bnShift+448+c);
    float4 f=*(const float4*)(feat+(size_t)n*64+c);
    float4 o=bnrelu4(z,sc,sh);
    o.x+=f.x; o.y+=f.y; o.z+=f.z; o.w+=f.w;
    *(float4*)(g_fused+(size_t)n*64+c)=o;
}

// pass 0: h1 = conv1(fused);  pass 1: h2 = conv2(relu(bn1(h1))) — bn1 applied in gather
__global__ void k_conv(int pass, const int* __restrict__ nbr, const float* __restrict__ W){
    __shared__ float At[64*68];
    __shared__ float Bs[64*64];
    __shared__ int nb[64*27];
    __shared__ float psc[64], psh[64];
    const float* fin = pass ? g_h1 : g_fused;
    float* outp = pass ? g_h2 : g_h1;
    int preOff = pass ? 512 : -1;
    int statsOff = pass ? 576 : 512;
    int r0=blockIdx.x*64, tid=threadIdx.x;
    for(int li=tid;li<1728;li+=256){
        size_t gi=(size_t)r0*27+li;
        nb[li]=(gi<(size_t)NPTS*27)? nbr[gi] : 0;
    }
    if(tid<64){
        psc[tid]=(preOff>=0)? g_bnScale[preOff+tid] : 1.f;
        psh[tid]=(preOff>=0)? g_bnShift[preOff+tid] : 0.f;
    }
    int ty=tid>>4, tx=tid&15, p=tid>>2, t4=tid&3, r=r0+p;
    float acc[4][4]={};
    for(int k=0;k<27;k++){
        __syncthreads();
        {
            int idx=nb[p*27+k];
            const float* src=fin+(size_t)idx*64;
#pragma unroll
            for(int v=0;v<4;v++){
                int j=t4*16+v*4;
                float4 a=make_float4(0,0,0,0);
                if(r<NPTS){
                    a=*(const float4*)(src+j);
                    if(preOff>=0){
                        a.x=fmaxf(fmaf(a.x,psc[j],psh[j]),0.f);
                        a.y=fmaxf(fmaf(a.y,psc[j+1],psh[j+1]),0.f);
                        a.z=fmaxf(fmaf(a.z,psc[j+2],psh[j+2]),0.f);
                        a.w=fmaxf(fmaf(a.w,psc[j+3],psh[j+3]),0.f);
                    }
                }
                storeT(At,j,p,a);
            }
            for(int li=tid;li<1024;li+=256)
                ((float4*)Bs)[li]=((const float4*)(W+k*4096))[li];
        }
        __syncthreads();
#pragma unroll 16
        for(int j=0;j<64;j++){
            float4 a=*(float4*)(At+j*68+ty*4);
            float4 b=*(float4*)(Bs+j*64+tx*4);
            fma16(acc,a,b);
        }
    }
#pragma unroll
    for(int u=0;u<4;u++){
        int rr=r0+ty*4+u;
        if(rr<NPTS)
            *(float4*)(outp+(size_t)rr*64+tx*4)=
                make_float4(acc[u][0],acc[u][1],acc[u][2],acc[u][3]);
    }
    __syncthreads();
    float* redS=Bs; float* redQ=Bs+1024;
    float s[4]={0,0,0,0}, q[4]={0,0,0,0};
#pragma unroll
    for(int u=0;u<4;u++)
#pragma unroll
        for(int cu=0;cu<4;cu++){ float v=acc[u][cu]; s[cu]+=v; q[cu]+=v*v; }
#pragma unroll
    for(int cu=0;cu<4;cu++){ redS[ty*64+tx*4+cu]=s[cu]; redQ[ty*64+tx*4+cu]=q[cu]; }
    __syncthreads();
    if(tid<64){
        float ss=0,qq=0;
#pragma unroll
        for(int y=0;y<16;y++){ ss+=redS[y*64+tid]; qq+=redQ[y*64+tid]; }
        atomicAdd(&g_colsum[statsOff+tid],ss);
        atomicAdd(&g_colsq[statsOff+tid],qq);
    }
}

__global__ void k_final(float* __restrict__ out){
    size_t i=(size_t)blockIdx.x*blockDim.x+threadIdx.x;
    if(i>=(size_t)NPTS*16) return;
    int n=(int)(i>>4); int c=((int)i&15)*4;
    float4 h=*(const float4*)(g_h2+(size_t)n*64+c);
    float4 sc=*(const float4*)(g_bnScale+576+c);
    float4 sh=*(const float4*)(g_bnShift+576+c);
    float4 f=*(const float4*)(g_fused+(size_t)n*64+c);
    float4 o;
    o.x=fmaxf(fmaf(h.x,sc.x,sh.x)+f.x,0.f);
    o.y=fmaxf(fmaf(h.y,sc.y,sh.y)+f.y,0.f);
    o.z=fmaxf(fmaf(h.z,sc.z,sh.z)+f.z,0.f);
    o.w=fmaxf(fmaf(h.w,sc.w,sh.w)+f.w,0.f);
    *(float4*)(out+(size_t)n*64+c)=o;
}

extern "C" void kernel_launch(void* const* d_in, const int* in_sizes, int n_in,
                              void* d_out, int out_size){
    const float* feat =(const float*)d_in[0];
    const int* c0=(const int*)d_in[1];
    const int* c1=(const int*)d_in[2];
    const int* c2=(const int*)d_in[3];
    const int* nbr=(const int*)d_in[4];
    const float* Wlw =(const float*)d_in[5];
    const float* glw =(const float*)d_in[6];
    const float* blw =(const float*)d_in[7];
    const float* Ww  =(const float*)d_in[8];
    const float* Wproj=(const float*)d_in[9];
    const float* gproj=(const float*)d_in[10];
    const float* bproj=(const float*)d_in[11];
    const float* Wadp=(const float*)d_in[12];
    const float* Wfuse=(const float*)d_in[13];
    const float* gfuse=(const float*)d_in[14];
    const float* bfuse=(const float*)d_in[15];
    const float* Wc1 =(const float*)d_in[16];
    const float* gc1 =(const float*)d_in[17];
    const float* bc1 =(const float*)d_in[18];
    const float* Wc2 =(const float*)d_in[19];
    const float* gc2 =(const float*)d_in[20];
    const float* bc2 =(const float*)d_in[21];
    float* out=(float*)d_out;

    k_zero_init<<<4096,256>>>();
    k_counts<<<(NPTS+255)/256,256>>>(c0,c1,c2);
    k_gemm_all<<<NT,256>>>(feat,Wlw,Wproj);
    k_bnparam448<<<2,256>>>(glw,blw,gproj,bproj);

    const int* cls[3]={c0,c1,c2};
    const int ncl[3]={NC0,NC1,NC2};
    const int cofs[3]={0,SEG1,SEG2};
    for(int i=0;i<3;i++){
        k_zero_segtmp<<<2048,256>>>((size_t)ncl[i]*64);
        k_pw_scatter<<<EWB,256>>>(cls[i], i*64, i*64);
        k_meansub_gemm<<<NT,256>>>(cls[i], Ww+i*4096, cofs[i], i);
        k_zero_segtmp<<<2048,256>>>((size_t)ncl[i]*64);
        k_exp_scatter<<<EWB,256>>>(cls[i], i);
        k_pfeat_scatter<<<EWB,256>>>(cls[i], 192+i*64, 192+i*64, (size_t)cofs[i]*64);
    }

    k_mix<<<NT,256>>>(feat,c0,c1,c2,Wadp);
    k_gemm128<<<NT,256>>>(Wfuse);
    k_bnparam64<<<1,64>>>(448,gfuse,bfuse);
    k_applyfuse<<<EWB,256>>>(feat);

    k_conv<<<NT,256>>>(0,nbr,Wc1);
    k_bnparam64<<<1,64>>>(512,gc1,bc1);
    k_conv<<<NT,256>>>(1,nbr,Wc2);
    k_bnparam64<<<1,64>>>(576,gc2,bc2);
    k_final<<<EWB,256>>>(out);
}

// round 7
// speedup vs baseline: 1.0123x; 1.0123x over previous
#include <cuda_runtime.h>
#include <cstdint>

#define NPTS 500000
#define NT 7813
#define EWB 31250
#define NC0 4096
#define NC1 32768
#define NC2 131072
#define SEG1 NC0
#define SEG2 (NC0+NC1)
#define SEGT (NC0+NC1+NC2)

__device__ float g_Y[(size_t)NPTS*448];
__device__ float g_pw[(size_t)NPTS*64];
__device__ float g_cat[(size_t)NPTS*128];
__device__ float g_z[(size_t)NPTS*64];
__device__ float g_fused[(size_t)NPTS*64];
__device__ float g_h1[(size_t)NPTS*64];
__device__ float g_h2[(size_t)NPTS*64];
__device__ float g_segTmp[(size_t)NC2*64];
__device__ float g_segP[(size_t)SEGT*64];
__device__ float g_cnt[SEGT];
__device__ float g_colsum[640];
__device__ float g_colsq[640];
__device__ float g_bnScale[640];
__device__ float g_bnShift[640];
__device__ unsigned g_maxbits[3];

typedef unsigned long long ull;

__device__ __forceinline__ unsigned fenc(float f){
    unsigned u=__float_as_uint(f);
    return (u&0x80000000u)? ~u : (u|0x80000000u);
}
__device__ __forceinline__ float fdec(unsigned v){
    unsigned u=(v&0x80000000u)? (v^0x80000000u) : ~v;
    return __uint_as_float(u);
}
__device__ __forceinline__ ull dup2(float x){
    ull r;
    asm("mov.b64 %0, {%1, %1};" : "=l"(r) : "r"(__float_as_uint(x)));
    return r;
}
__device__ __forceinline__ void ffma2(ull &acc, ull a, ull b){
    asm("fma.rn.f32x2 %0, %1, %2, %3;" : "=l"(acc) : "l"(a), "l"(b), "l"(acc));
}
__device__ __forceinline__ float lo2(ull v){ return __uint_as_float((unsigned)v); }
__device__ __forceinline__ float hi2(ull v){ return __uint_as_float((unsigned)(v>>32)); }

// packed 4x4 tile step: a = 4 row values, b = 4 col values (as 2 packed pairs)
__device__ __forceinline__ void fma16p(ull acc[4][2], float4 a, ulonglong2 b){
    ull a0=dup2(a.x), a1=dup2(a.y), a2=dup2(a.z), a3=dup2(a.w);
    ffma2(acc[0][0],a0,b.x); ffma2(acc[0][1],a0,b.y);
    ffma2(acc[1][0],a1,b.x); ffma2(acc[1][1],a1,b.y);
    ffma2(acc[2][0],a2,b.x); ffma2(acc[2][1],a2,b.y);
    ffma2(acc[3][0],a3,b.x); ffma2(acc[3][1],a3,b.y);
}
__device__ __forceinline__ float4 row4(ull* accu){
    return make_float4(lo2(accu[0]),hi2(accu[0]),lo2(accu[1]),hi2(accu[1]));
}
__device__ __forceinline__ float4 bnrelu4(float4 y, float4 sc, float4 sh){
    float4 o;
    o.x=fmaxf(fmaf(y.x,sc.x,sh.x),0.f); o.y=fmaxf(fmaf(y.y,sc.y,sh.y),0.f);
    o.z=fmaxf(fmaf(y.z,sc.z,sh.z),0.f); o.w=fmaxf(fmaf(y.w,sc.w,sh.w),0.f);
    return o;
}
__device__ __forceinline__ void storeT(float* At, int j, int p, float4 a){
    At[(j+0)*68+p]=a.x; At[(j+1)*68+p]=a.y; At[(j+2)*68+p]=a.z; At[(j+3)*68+p]=a.w;
}

__global__ void k_zero_init(){
    size_t i=(size_t)blockIdx.x*blockDim.x+threadIdx.x;
    size_t stride=(size_t)gridDim.x*blockDim.x;
    for(size_t j=i;j<(size_t)SEGT*64;j+=stride) g_segP[j]=0.f;
    if(i<SEGT) g_cnt[i]=0.f;
    if(i<640){ g_colsum[i]=0.f; g_colsq[i]=0.f; }
    if(i<3) g_maxbits[i]=0u;
}
__global__ void k_zero_segtmp(size_t n){
    size_t i=(size_t)blockIdx.x*blockDim.x+threadIdx.x;
    size_t stride=(size_t)gridDim.x*blockDim.x;
    for(size_t j=i;j<n;j+=stride) g_segTmp[j]=0.f;
}
__global__ void k_counts(const int* __restrict__ c0, const int* __restrict__ c1,
                         const int* __restrict__ c2){
    int n=blockIdx.x*blockDim.x+threadIdx.x;
    if(n<NPTS){
        atomicAdd(&g_cnt[c0[n]],1.f);
        atomicAdd(&g_cnt[SEG1+c1[n]],1.f);
        atomicAdd(&g_cnt[SEG2+c2[n]],1.f);
    }
}

// feat @ [W_lw0..2 | W_proj0..3], BN-stats epilogue
__global__ void k_gemm_all(const float* __restrict__ feat, const float* __restrict__ Wlw,
                           const float* __restrict__ Wproj){
    __shared__ float At[64*68];
    __shared__ float Bs[64*64];
    __shared__ float redS[16*64];
    __shared__ float redQ[16*64];
    int r0=blockIdx.x*64, tid=threadIdx.x;
    int p=tid>>2, t4=tid&3, r=r0+p;
    int ty=tid>>4, tx=tid&15;
#pragma unroll
    for(int v=0;v<4;v++){
        int j=t4*16+v*4;
        float4 a=(r<NPTS)? *(const float4*)(feat+(size_t)r*64+j) : make_float4(0,0,0,0);
        storeT(At,j,p,a);
    }
    for(int t=0;t<7;t++){
        const float* W=(t<3)? (Wlw+t*4096) : (Wproj+(t-3)*4096);
        __syncthreads();
        for(int li=tid;li<1024;li+=256) ((float4*)Bs)[li]=((const float4*)W)[li];
        __syncthreads();
        ull acc[4][2]={};
#pragma unroll 16
        for(int j=0;j<64;j++){
            float4 a=*(float4*)(At+j*68+ty*4);
            ulonglong2 b=*(ulonglong2*)(Bs+j*64+tx*4);
            fma16p(acc,a,b);
        }
        float s[4]={0,0,0,0}, q[4]={0,0,0,0};
#pragma unroll
        for(int u=0;u<4;u++){
            float4 o=row4(acc[u]);
            int rr=r0+ty*4+u;
            if(rr<NPTS)
                *(float4*)(g_Y+(size_t)rr*448+t*64+tx*4)=o;
            s[0]+=o.x; q[0]+=o.x*o.x; s[1]+=o.y; q[1]+=o.y*o.y;
            s[2]+=o.z; q[2]+=o.z*o.z; s[3]+=o.w; q[3]+=o.w*o.w;
        }
#pragma unroll
        for(int cu=0;cu<4;cu++){ redS[ty*64+tx*4+cu]=s[cu]; redQ[ty*64+tx*4+cu]=q[cu]; }
        __syncthreads();
        if(tid<64){
            float ss=0,qq=0;
#pragma unroll
            for(int y=0;y<16;y++){ ss+=redS[y*64+tid]; qq+=redQ[y*64+tid]; }
            atomicAdd(&g_colsum[t*64+tid],ss);
            atomicAdd(&g_colsq[t*64+tid],qq);
        }
    }
}

__global__ void k_bnparam448(const float* __restrict__ glw, const float* __restrict__ blw,
                             const float* __restrict__ gproj, const float* __restrict__ bproj){
    int c=blockIdx.x*blockDim.x+threadIdx.x;
    if(c>=448) return;
    int grp=c>>6, ch=c&63;
    float g=(grp<3)? glw[grp*64+ch] : gproj[(grp-3)*64+ch];
    float b=(grp<3)? blw[grp*64+ch] : bproj[(grp-3)*64+ch];
    float inv=1.0f/(float)NPTS;
    float mu=g_colsum[c]*inv;
    float var=g_colsq[c]*inv-mu*mu;
    float sc=g*rsqrtf(var+1e-3f);
    g_bnScale[c]=sc; g_bnShift[c]=b-mu*sc;
}
__global__ void k_bnparam64(int off, const float* __restrict__ g, const float* __restrict__ b){
    int c=threadIdx.x;
    if(c>=64) return;
    float inv=1.0f/(float)NPTS;
    float mu=g_colsum[off+c]*inv;
    float var=g_colsq[off+c]*inv-mu*mu;
    float sc=g[c]*rsqrtf(var+1e-3f);
    g_bnScale[off+c]=sc; g_bnShift[off+c]=b[c]-mu*sc;
}

__global__ void k_pw_scatter(const int* __restrict__ cl, int ycol, int bnoff){
    size_t i=(size_t)blockIdx.x*blockDim.x+threadIdx.x;
    if(i>=(size_t)NPTS*16) return;
    int n=(int)(i>>4); int c=((int)i&15)*4;
    float4 y=*(const float4*)(g_Y+(size_t)n*448+ycol+c);
    float4 sc=*(const float4*)(g_bnScale+bnoff+c);
    float4 sh=*(const float4*)(g_bnShift+bnoff+c);
    float4 o=bnrelu4(y,sc,sh);
    *(float4*)(g_pw+(size_t)n*64+c)=o;
    float* seg=g_segTmp+(size_t)cl[n]*64+c;
    atomicAdd(seg,o.x); atomicAdd(seg+1,o.y); atomicAdd(seg+2,o.z); atomicAdd(seg+3,o.w);
}

__global__ void k_meansub_gemm(const int* __restrict__ cl, const float* __restrict__ Ww,
                               int cntOff, int maxIdx){
    __shared__ float At[64*68];
    __shared__ float Bs[64*64];
    __shared__ float wmax[8];
    int r0=blockIdx.x*64, tid=threadIdx.x;
    int p=tid>>2, t4=tid&3, r=r0+p;
    {
        int s=0; float inv=0.f;
        if(r<NPTS){ s=cl[r]; inv=1.f/fmaxf(g_cnt[cntOff+s],1.f); }
#pragma unroll
        for(int v=0;v<4;v++){
            int j=t4*16+v*4;
            float4 a=make_float4(0,0,0,0);
            if(r<NPTS){
                float4 pw=*(const float4*)(g_pw+(size_t)r*64+j);
                float4 m=*(const float4*)(g_segTmp+(size_t)s*64+j);
                a.x=pw.x-m.x*inv; a.y=pw.y-m.y*inv; a.z=pw.z-m.z*inv; a.w=pw.w-m.w*inv;
            }
            storeT(At,j,p,a);
        }
    }
    for(int li=tid;li<1024;li+=256) ((float4*)Bs)[li]=((const float4*)Ww)[li];
    __syncthreads();
    int ty=tid>>4, tx=tid&15;
    ull acc[4][2]={};
#pragma unroll 16
    for(int j=0;j<64;j++){
        float4 a=*(float4*)(At+j*68+ty*4);
        ulonglong2 b=*(ulonglong2*)(Bs+j*64+tx*4);
        fma16p(acc,a,b);
    }
    float m=-3.0e38f;
#pragma unroll
    for(int u=0;u<4;u++){
        int rr=r0+ty*4+u;
        if(rr<NPTS){
            float4 o=row4(acc[u]);
            *(float4*)(g_pw+(size_t)rr*64+tx*4)=o;
            m=fmaxf(m,fmaxf(fmaxf(o.x,o.y),fmaxf(o.z,o.w)));
        }
    }
#pragma unroll
    for(int o=16;o>0;o>>=1) m=fmaxf(m,__shfl_down_sync(0xffffffffu,m,o));
    if((tid&31)==0) wmax[tid>>5]=m;
    __syncthreads();
    if(tid==0){
        float mm=wmax[0];
#pragma unroll
        for(int w=1;w<8;w++) mm=fmaxf(mm,wmax[w]);
        atomicMax(&g_maxbits[maxIdx],fenc(mm));
    }
}

__global__ void k_exp_scatter(const int* __restrict__ cl, int maxIdx){
    size_t i=(size_t)blockIdx.x*blockDim.x+threadIdx.x;
    if(i>=(size_t)NPTS*16) return;
    int n=(int)(i>>4); int c=((int)i&15)*4;
    float gmax=fdec(g_maxbits[maxIdx]);
    float4 v=*(float4*)(g_pw+(size_t)n*64+c);
    v.x=__expf(v.x-gmax); v.y=__expf(v.y-gmax); v.z=__expf(v.z-gmax); v.w=__expf(v.w-gmax);
    *(float4*)(g_pw+(size_t)n*64+c)=v;
    float* seg=g_segTmp+(size_t)cl[n]*64+c;
    atomicAdd(seg,v.x); atomicAdd(seg+1,v.y); atomicAdd(seg+2,v.z); atomicAdd(seg+3,v.w);
}

__global__ void k_pfeat_scatter(const int* __restrict__ cl, int ycol, int bnoff, size_t segOff){
    size_t i=(size_t)blockIdx.x*blockDim.x+threadIdx.x;
    if(i>=(size_t)NPTS*16) return;
    int n=(int)(i>>4); int c=((int)i&15)*4;
    float4 y=*(const float4*)(g_Y+(size_t)n*448+ycol+c);
    float4 sc=*(const float4*)(g_bnScale+bnoff+c);
    float4 sh=*(const float4*)(g_bnShift+bnoff+c);
    float4 o=bnrelu4(y,sc,sh);
    float4 e=*(const float4*)(g_pw+(size_t)n*64+c);
    int s=cl[n];
    float4 d=*(const float4*)(g_segTmp+(size_t)s*64+c);
    float4 val;
    val.x=o.x*e.x/(d.x+1e-6f); val.y=o.y*e.y/(d.y+1e-6f);
    val.z=o.z*e.z/(d.z+1e-6f); val.w=o.w*e.w/(d.w+1e-6f);
    float* seg=g_segP+segOff+(size_t)s*64+c;
    atomicAdd(seg,val.x); atomicAdd(seg+1,val.y); atomicAdd(seg+2,val.z); atomicAdd(seg+3,val.w);
}

__global__ void k_mix(const float* __restrict__ feat, const int* __restrict__ c0,
                      const int* __restrict__ c1, const int* __restrict__ c2,
                      const float* __restrict__ Wadp){
    __shared__ float ft[64*68];
    __shared__ float wa[192];
    __shared__ float adp[64*3];
    int r0=blockIdx.x*64, tid=threadIdx.x;
    int p=tid>>2, t4=tid&3, r=r0+p;
    if(tid<192) wa[tid]=Wadp[tid];
#pragma unroll
    for(int v=0;v<4;v++){
        int j=t4*16+v*4;
        float4 a=(r<NPTS)? *(const float4*)(feat+(size_t)r*64+j) : make_float4(0,0,0,0);
        *(float4*)(ft+p*68+j)=a;
    }
    __syncthreads();
    if(tid<64){
        float l0=0,l1=0,l2=0;
#pragma unroll 16
        for(int j=0;j<64;j++){
            float f=ft[tid*68+j];
            l0=fmaf(f,wa[j*3],l0); l1=fmaf(f,wa[j*3+1],l1); l2=fmaf(f,wa[j*3+2],l2);
        }
        float mx=fmaxf(l0,fmaxf(l1,l2));
        float e0=__expf(l0-mx), e1=__expf(l1-mx), e2=__expf(l2-mx);
        float inv=1.f/(e0+e1+e2);
        adp[tid*3]=e0*inv; adp[tid*3+1]=e1*inv; adp[tid*3+2]=e2*inv;
    }
    __syncthreads();
    if(r>=NPTS) return;
    float w0=adp[p*3], w1=adp[p*3+1], w2=adp[p*3+2];
    size_t b0=(size_t)c0[r]*64;
    size_t b1=(size_t)(SEG1+c1[r])*64;
    size_t b2=(size_t)(SEG2+c2[r])*64;
#pragma unroll
    for(int v=0;v<4;v++){
        int c=t4*16+v*4;
        float4 y=*(const float4*)(g_Y+(size_t)r*448+384+c);
        float4 sc=*(const float4*)(g_bnScale+384+c);
        float4 sh=*(const float4*)(g_bnShift+384+c);
        float4 fl=bnrelu4(y,sc,sh);
        float4 a0=*(const float4*)(g_segP+b0+c);
        float4 a1=*(const float4*)(g_segP+b1+c);
        float4 a2=*(const float4*)(g_segP+b2+c);
        float4 m;
        m.x=w0*a0.x+w1*a1.x+w2*a2.x; m.y=w0*a0.y+w1*a1.y+w2*a2.y;
        m.z=w0*a0.z+w1*a1.z+w2*a2.z; m.w=w0*a0.w+w1*a1.w+w2*a2.w;
        *(float4*)(g_cat+(size_t)r*128+c)=fl;
        *(float4*)(g_cat+(size_t)r*128+64+c)=m;
    }
}

__global__ void k_gemm128(const float* __restrict__ Wfuse){
    __shared__ float At[64*68];
    __shared__ float Bs[64*64];
    int r0=blockIdx.x*64, tid=threadIdx.x;
    int p=tid>>2, t4=tid&3, r=r0+p;
    int ty=tid>>4, tx=tid&15;
    ull acc[4][2]={};
    for(int kc=0;kc<2;kc++){
        __syncthreads();
#pragma unroll
        for(int v=0;v<4;v++){
            int j=t4*16+v*4;
            float4 a=(r<NPTS)? *(const float4*)(g_cat+(size_t)r*128+kc*64+j)
                             : make_float4(0,0,0,0);
            storeT(At,j,p,a);
        }
        for(int li=tid;li<1024;li+=256) ((float4*)Bs)[li]=((const float4*)(Wfuse+kc*4096))[li];
        __syncthreads();
#pragma unroll 16
        for(int j=0;j<64;j++){
            float4 a=*(float4*)(At+j*68+ty*4);
            ulonglong2 b=*(ulonglong2*)(Bs+j*64+tx*4);
            fma16p(acc,a,b);
        }
    }
    float s[4]={0,0,0,0}, q[4]={0,0,0,0};
#pragma unroll
    for(int u=0;u<4;u++){
        float4 o=row4(acc[u]);
        int rr=r0+ty*4+u;
        if(rr<NPTS)
            *(float4*)(g_z+(size_t)rr*64+tx*4)=o;
        s[0]+=o.x; q[0]+=o.x*o.x; s[1]+=o.y; q[1]+=o.y*o.y;
        s[2]+=o.z; q[2]+=o.z*o.z; s[3]+=o.w; q[3]+=o.w*o.w;
    }
    __syncthreads();
    float* redS=At; float* redQ=At+1024;
#pragma unroll
    for(int cu=0;cu<4;cu++){ redS[ty*64+tx*4+cu]=s[cu]; redQ[ty*64+tx*4+cu]=q[cu]; }
    __syncthreads();
    if(tid<64){
        float ss=0,qq=0;
#pragma unroll
        for(int y=0;y<16;y++){ ss+=redS[y*64+tid]; qq+=redQ[y*64+tid]; }
        atomicAdd(&g_colsum[448+tid],ss);
        atomicAdd(&g_colsq[448+tid],qq);
    }
}

__global__ void k_applyfuse(const float* __restrict__ feat){
    size_t i=(size_t)blockIdx.x*blockDim.x+threadIdx.x;
    if(i>=(size_t)NPTS*16) return;
    int n=(int)(i>>4); int c=((int)i&15)*4;
    float4 z=*(const float4*)(g_z+(size_t)n*64+c);
    float4 sc=*(const float4*)(g_bnScale+448+c);
    float4 sh=*(const float4*)(g_bnShift+448+c);
    float4 f=*(const float4*)(feat+(size_t)n*64+c);
    float4 o=bnrelu4(z,sc,sh);
    o.x+=f.x; o.y+=f.y; o.z+=f.z; o.w+=f.w;
    *(float4*)(g_fused+(size_t)n*64+c)=o;
}

// pass 0: h1 = conv1(fused);  pass 1: h2 = conv2(relu(bn1(h1))) — bn1 applied in gather
__global__ void k_conv(int pass, const int* __restrict__ nbr, const float* __restrict__ W){
    __shared__ float At[64*68];
    __shared__ float Bs[64*64];
    __shared__ int nb[64*27];
    __shared__ float psc[64], psh[64];
    const float* fin = pass ? g_h1 : g_fused;
    float* outp = pass ? g_h2 : g_h1;
    int preOff = pass ? 512 : -1;
    int statsOff = pass ? 576 : 512;
    int r0=blockIdx.x*64, tid=threadIdx.x;
    for(int li=tid;li<1728;li+=256){
        size_t gi=(size_t)r0*27+li;
        nb[li]=(gi<(size_t)NPTS*27)? nbr[gi] : 0;
    }
    if(tid<64){
        psc[tid]=(preOff>=0)? g_bnScale[preOff+tid] : 1.f;
        psh[tid]=(preOff>=0)? g_bnShift[preOff+tid] : 0.f;
    }
    int ty=tid>>4, tx=tid&15, p=tid>>2, t4=tid&3, r=r0+p;
    ull acc[4][2]={};
    for(int k=0;k<27;k++){
        __syncthreads();
        {
            int idx=nb[p*27+k];
            const float* src=fin+(size_t)idx*64;
#pragma unroll
            for(int v=0;v<4;v++){
                int j=t4*16+v*4;
                float4 a=make_float4(0,0,0,0);
                if(r<NPTS){
                    a=*(const float4*)(src+j);
                    if(preOff>=0){
                        a.x=fmaxf(fmaf(a.x,psc[j],psh[j]),0.f);
                        a.y=fmaxf(fmaf(a.y,psc[j+1],psh[j+1]),0.f);
                        a.z=fmaxf(fmaf(a.z,psc[j+2],psh[j+2]),0.f);
                        a.w=fmaxf(fmaf(a.w,psc[j+3],psh[j+3]),0.f);
                    }
                }
                storeT(At,j,p,a);
            }
            for(int li=tid;li<1024;li+=256)
                ((float4*)Bs)[li]=((const float4*)(W+k*4096))[li];
        }
        __syncthreads();
#pragma unroll 16
        for(int j=0;j<64;j++){
            float4 a=*(float4*)(At+j*68+ty*4);
            ulonglong2 b=*(ulonglong2*)(Bs+j*64+tx*4);
            fma16p(acc,a,b);
        }
    }
    float s[4]={0,0,0,0}, q[4]={0,0,0,0};
#pragma unroll
    for(int u=0;u<4;u++){
        float4 o=row4(acc[u]);
        int rr=r0+ty*4+u;
        if(rr<NPTS)
            *(float4*)(outp+(size_t)rr*64+tx*4)=o;
        s[0]+=o.x; q[0]+=o.x*o.x; s[1]+=o.y; q[1]+=o.y*o.y;
        s[2]+=o.z; q[2]+=o.z*o.z; s[3]+=o.w; q[3]+=o.w*o.w;
    }
    __syncthreads();
    float* redS=Bs; float* redQ=Bs+1024;
#pragma unroll
    for(int cu=0;cu<4;cu++){ redS[ty*64+tx*4+cu]=s[cu]; redQ[ty*64+tx*4+cu]=q[cu]; }
    __syncthreads();
    if(tid<64){
        float ss=0,qq=0;
#pragma unroll
        for(int y=0;y<16;y++){ ss+=redS[y*64+tid]; qq+=redQ[y*64+tid]; }
        atomicAdd(&g_colsum[statsOff+tid],ss);
        atomicAdd(&g_colsq[statsOff+tid],qq);
    }
}

__global__ void k_final(float* __restrict__ out){
    size_t i=(size_t)blockIdx.x*blockDim.x+threadIdx.x;
    if(i>=(size_t)NPTS*16) return;
    int n=(int)(i>>4); int c=((int)i&15)*4;
    float4 h=*(const float4*)(g_h2+(size_t)n*64+c);
    float4 sc=*(const float4*)(g_bnScale+576+c);
    float4 sh=*(const float4*)(g_bnShift+576+c);
    float4 f=*(const float4*)(g_fused+(size_t)n*64+c);
    float4 o;
    o.x=fmaxf(fmaf(h.x,sc.x,sh.x)+f.x,0.f);
    o.y=fmaxf(fmaf(h.y,sc.y,sh.y)+f.y,0.f);
    o.z=fmaxf(fmaf(h.z,sc.z,sh.z)+f.z,0.f);
    o.w=fmaxf(fmaf(h.w,sc.w,sh.w)+f.w,0.f);
    *(float4*)(out+(size_t)n*64+c)=o;
}

extern "C" void kernel_launch(void* const* d_in, const int* in_sizes, int n_in,
                              void* d_out, int out_size){
    const float* feat =(const float*)d_in[0];
    const int* c0=(const int*)d_in[1];
    const int* c1=(const int*)d_in[2];
    const int* c2=(const int*)d_in[3];
    const int* nbr=(const int*)d_in[4];
    const float* Wlw =(const float*)d_in[5];
    const float* glw =(const float*)d_in[6];
    const float* blw =(const float*)d_in[7];
    const float* Ww  =(const float*)d_in[8];
    const float* Wproj=(const float*)d_in[9];
    const float* gproj=(const float*)d_in[10];
    const float* bproj=(const float*)d_in[11];
    const float* Wadp=(const float*)d_in[12];
    const float* Wfuse=(const float*)d_in[13];
    const float* gfuse=(const float*)d_in[14];
    const float* bfuse=(const float*)d_in[15];
    const float* Wc1 =(const float*)d_in[16];
    const float* gc1 =(const float*)d_in[17];
    const float* bc1 =(const float*)d_in[18];
    const float* Wc2 =(const float*)d_in[19];
    const float* gc2 =(const float*)d_in[20];
    const float* bc2 =(const float*)d_in[21];
    float* out=(float*)d_out;

    k_zero_init<<<4096,256>>>();
    k_counts<<<(NPTS+255)/256,256>>>(c0,c1,c2);
    k_gemm_all<<<NT,256>>>(feat,Wlw,Wproj);
    k_bnparam448<<<2,256>>>(glw,blw,gproj,bproj);

    const int* cls[3]={c0,c1,c2};
    const int ncl[3]={NC0,NC1,NC2};
    const int cofs[3]={0,SEG1,SEG2};
    for(int i=0;i<3;i++){
        k_zero_segtmp<<<2048,256>>>((size_t)ncl[i]*64);
        k_pw_scatter<<<EWB,256>>>(cls[i], i*64, i*64);
        k_meansub_gemm<<<NT,256>>>(cls[i], Ww+i*4096, cofs[i], i);
        k_zero_segtmp<<<2048,256>>>((size_t)ncl[i]*64);
        k_exp_scatter<<<EWB,256>>>(cls[i], i);
        k_pfeat_scatter<<<EWB,256>>>(cls[i], 192+i*64, 192+i*64, (size_t)cofs[i]*64);
    }

    k_mix<<<NT,256>>>(feat,c0,c1,c2,Wadp);
    k_gemm128<<<NT,256>>>(Wfuse);
    k_bnparam64<<<1,64>>>(448,gfuse,bfuse);
    k_applyfuse<<<EWB,256>>>(feat);

    k_conv<<<NT,256>>>(0,nbr,Wc1);
    k_bnparam64<<<1,64>>>(512,gc1,bc1);
    k_conv<<<NT,256>>>(1,nbr,Wc2);
    k_bnparam64<<<1,64>>>(576,gc2,bc2);
    k_final<<<EWB,256>>>(out);
}

// round 10
// speedup vs baseline: 1.0492x; 1.0364x over previous
#include <cuda_runtime.h>
#include <cstdint>

#define NPTS 500000
#define NT 7813
#define EWB 31250
#define NC0 4096
#define NC1 32768
#define NC2 131072
#define SEG1 NC0
#define SEG2 (NC0+NC1)
#define SEGT (NC0+NC1+NC2)

__device__ __align__(16) float g_Y[(size_t)NPTS*448];
__device__ __align__(16) float g_pw[(size_t)NPTS*64];
__device__ __align__(16) float g_cat[(size_t)NPTS*128];
__device__ __align__(16) float g_z[(size_t)NPTS*64];
__device__ __align__(16) float g_fused[(size_t)NPTS*64];
__device__ __align__(16) float g_h1[(size_t)NPTS*64];
__device__ __align__(16) float g_h2[(size_t)NPTS*64];
__device__ __align__(16) float g_segTmp[(size_t)NC2*64];
__device__ __align__(16) float g_segP[(size_t)SEGT*64];
__device__ float g_cnt[SEGT];
__device__ float g_colsum[640];
__device__ float g_colsq[640];
__device__ float g_bnScale[640];
__device__ float g_bnShift[640];
__device__ unsigned g_maxbits[3];

typedef unsigned long long ull;

__device__ __forceinline__ unsigned fenc(float f){
    unsigned u=__float_as_uint(f);
    return (u&0x80000000u)? ~u : (u|0x80000000u);
}
__device__ __forceinline__ float fdec(unsigned v){
    unsigned u=(v&0x80000000u)? (v^0x80000000u) : ~v;
    return __uint_as_float(u);
}
__device__ __forceinline__ void red4(float* addr, float4 v){
    asm volatile("red.global.add.v4.f32 [%0], {%1,%2,%3,%4};"
        :: "l"(addr), "f"(v.x), "f"(v.y), "f"(v.z), "f"(v.w) : "memory");
}
__device__ __forceinline__ ull dup2(float x){
    ull r;
    asm("mov.b64 %0, {%1, %1};" : "=l"(r) : "r"(__float_as_uint(x)));
    return r;
}
__device__ __forceinline__ void ffma2(ull &acc, ull a, ull b){
    asm("fma.rn.f32x2 %0, %1, %2, %3;" : "=l"(acc) : "l"(a), "l"(b), "l"(acc));
}
__device__ __forceinline__ float lo2(ull v){ return __uint_as_float((unsigned)v); }
__device__ __forceinline__ float hi2(ull v){ return __uint_as_float((unsigned)(v>>32)); }

__device__ __forceinline__ void fma16p(ull acc[4][2], float4 a, ulonglong2 b){
    ull a0=dup2(a.x), a1=dup2(a.y), a2=dup2(a.z), a3=dup2(a.w);
    ffma2(acc[0][0],a0,b.x); ffma2(acc[0][1],a0,b.y);
    ffma2(acc[1][0],a1,b.x); ffma2(acc[1][1],a1,b.y);
    ffma2(acc[2][0],a2,b.x); ffma2(acc[2][1],a2,b.y);
    ffma2(acc[3][0],a3,b.x); ffma2(acc[3][1],a3,b.y);
}
__device__ __forceinline__ float4 row4(ull* accu){
    return make_float4(lo2(accu[0]),hi2(accu[0]),lo2(accu[1]),hi2(accu[1]));
}
__device__ __forceinline__ float4 bnrelu4(float4 y, float4 sc, float4 sh){
    float4 o;
    o.x=fmaxf(fmaf(y.x,sc.x,sh.x),0.f); o.y=fmaxf(fmaf(y.y,sc.y,sh.y),0.f);
    o.z=fmaxf(fmaf(y.z,sc.z,sh.z),0.f); o.w=fmaxf(fmaf(y.w,sc.w,sh.w),0.f);
    return o;
}
__device__ __forceinline__ void storeT(float* At, int j, int p, float4 a){
    At[(j+0)*68+p]=a.x; At[(j+1)*68+p]=a.y; At[(j+2)*68+p]=a.z; At[(j+3)*68+p]=a.w;
}

__global__ void k_zero_init(){
    size_t i=(size_t)blockIdx.x*blockDim.x+threadIdx.x;
    size_t stride=(size_t)gridDim.x*blockDim.x;
    for(size_t j=i;j<(size_t)SEGT*64;j+=stride) g_segP[j]=0.f;
    if(i<SEGT) g_cnt[i]=0.f;
    if(i<640){ g_colsum[i]=0.f; g_colsq[i]=0.f; }
    if(i<3) g_maxbits[i]=0u;
}
__global__ void k_zero_segtmp(size_t n){
    size_t i=(size_t)blockIdx.x*blockDim.x+threadIdx.x;
    size_t stride=(size_t)gridDim.x*blockDim.x;
    for(size_t j=i;j<n;j+=stride) g_segTmp[j]=0.f;
}
__global__ void k_counts(const int* __restrict__ c0, const int* __restrict__ c1,
                         const int* __restrict__ c2){
    int n=blockIdx.x*blockDim.x+threadIdx.x;
    if(n<NPTS){
        atomicAdd(&g_cnt[c0[n]],1.f);
        atomicAdd(&g_cnt[SEG1+c1[n]],1.f);
        atomicAdd(&g_cnt[SEG2+c2[n]],1.f);
    }
}

__global__ void k_gemm_all(const float* __restrict__ feat, const float* __restrict__ Wlw,
                           const float* __restrict__ Wproj){
    __shared__ float At[64*68];
    __shared__ float Bs[64*64];
    __shared__ float redS[16*64];
    __shared__ float redQ[16*64];
    int r0=blockIdx.x*64, tid=threadIdx.x;
    int p=tid>>2, t4=tid&3, r=r0+p;
    int ty=tid>>4, tx=tid&15;
#pragma unroll
    for(int v=0;v<4;v++){
        int j=t4*16+v*4;
        float4 a=(r<NPTS)? *(const float4*)(feat+(size_t)r*64+j) : make_float4(0,0,0,0);
        storeT(At,j,p,a);
    }
    for(int t=0;t<7;t++){
        const float* W=(t<3)? (Wlw+t*4096) : (Wproj+(t-3)*4096);
        __syncthreads();
        for(int li=tid;li<1024;li+=256) ((float4*)Bs)[li]=((const float4*)W)[li];
        __syncthreads();
        ull acc[4][2]={};
#pragma unroll 16
        for(int j=0;j<64;j++){
            float4 a=*(float4*)(At+j*68+ty*4);
            ulonglong2 b=*(ulonglong2*)(Bs+j*64+tx*4);
            fma16p(acc,a,b);
        }
        float s[4]={0,0,0,0}, q[4]={0,0,0,0};
#pragma unroll
        for(int u=0;u<4;u++){
            float4 o=row4(acc[u]);
            int rr=r0+ty*4+u;
            if(rr<NPTS)
                *(float4*)(g_Y+(size_t)rr*448+t*64+tx*4)=o;
            s[0]+=o.x; q[0]+=o.x*o.x; s[1]+=o.y; q[1]+=o.y*o.y;
            s[2]+=o.z; q[2]+=o.z*o.z; s[3]+=o.w; q[3]+=o.w*o.w;
        }
#pragma unroll
        for(int cu=0;cu<4;cu++){ redS[ty*64+tx*4+cu]=s[cu]; redQ[ty*64+tx*4+cu]=q[cu]; }
        __syncthreads();
        if(tid<64){
            float ss=0,qq=0;
#pragma unroll
            for(int y=0;y<16;y++){ ss+=redS[y*64+tid]; qq+=redQ[y*64+tid]; }
            atomicAdd(&g_colsum[t*64+tid],ss);
            atomicAdd(&g_colsq[t*64+tid],qq);
        }
    }
}

__global__ void k_bnparam448(const float* __restrict__ glw, const float* __restrict__ blw,
                             const float* __restrict__ gproj, const float* __restrict__ bproj){
    int c=blockIdx.x*blockDim.x+threadIdx.x;
    if(c>=448) return;
    int grp=c>>6, ch=c&63;
    float g=(grp<3)? glw[grp*64+ch] : gproj[(grp-3)*64+ch];
    float b=(grp<3)? blw[grp*64+ch] : bproj[(grp-3)*64+ch];
    float inv=1.0f/(float)NPTS;
    float mu=g_colsum[c]*inv;
    float var=g_colsq[c]*inv-mu*mu;
    float sc=g*rsqrtf(var+1e-3f);
    g_bnScale[c]=sc; g_bnShift[c]=b-mu*sc;
}
__global__ void k_bnparam64(int off, const float* __restrict__ g, const float* __restrict__ b){
    int c=threadIdx.x;
    if(c>=64) return;
    float inv=1.0f/(float)NPTS;
    float mu=g_colsum[off+c]*inv;
    float var=g_colsq[off+c]*inv-mu*mu;
    float sc=g[c]*rsqrtf(var+1e-3f);
    g_bnScale[off+c]=sc; g_bnShift[off+c]=b[c]-mu*sc;
}

__global__ void k_pw_scatter(const int* __restrict__ cl, int ycol, int bnoff){
    size_t i=(size_t)blockIdx.x*blockDim.x+threadIdx.x;
    if(i>=(size_t)NPTS*16) return;
    int n=(int)(i>>4); int c=((int)i&15)*4;
    float4 y=*(const float4*)(g_Y+(size_t)n*448+ycol+c);
    float4 sc=*(const float4*)(g_bnScale+bnoff+c);
    float4 sh=*(const float4*)(g_bnShift+bnoff+c);
    float4 o=bnrelu4(y,sc,sh);
    *(float4*)(g_pw+(size_t)n*64+c)=o;
    red4(g_segTmp+(size_t)cl[n]*64+c, o);
}

__global__ void k_meansub_gemm(const int* __restrict__ cl, const float* __restrict__ Ww,
                               int cntOff, int maxIdx){
    __shared__ float At[64*68];
    __shared__ float Bs[64*64];
    __shared__ float wmax[8];
    int r0=blockIdx.x*64, tid=threadIdx.x;
    int p=tid>>2, t4=tid&3, r=r0+p;
    {
        int s=0; float inv=0.f;
        if(r<NPTS){ s=cl[r]; inv=1.f/fmaxf(g_cnt[cntOff+s],1.f); }
#pragma unroll
        for(int v=0;v<4;v++){
            int j=t4*16+v*4;
            float4 a=make_float4(0,0,0,0);
            if(r<NPTS){
                float4 pw=*(const float4*)(g_pw+(size_t)r*64+j);
                float4 m=*(const float4*)(g_segTmp+(size_t)s*64+j);
                a.x=pw.x-m.x*inv; a.y=pw.y-m.y*inv; a.z=pw.z-m.z*inv; a.w=pw.w-m.w*inv;
            }
            storeT(At,j,p,a);
        }
    }
    for(int li=tid;li<1024;li+=256) ((float4*)Bs)[li]=((const float4*)Ww)[li];
    __syncthreads();
    int ty=tid>>4, tx=tid&15;
    ull acc[4][2]={};
#pragma unroll 16
    for(int j=0;j<64;j++){
        float4 a=*(float4*)(At+j*68+ty*4);
        ulonglong2 b=*(ulonglong2*)(Bs+j*64+tx*4);
        fma16p(acc,a,b);
    }
    float m=-3.0e38f;
#pragma unroll
    for(int u=0;u<4;u++){
        int rr=r0+ty*4+u;
        if(rr<NPTS){
            float4 o=row4(acc[u]);
            *(float4*)(g_pw+(size_t)rr*64+tx*4)=o;
            m=fmaxf(m,fmaxf(fmaxf(o.x,o.y),fmaxf(o.z,o.w)));
        }
    }
#pragma unroll
    for(int o=16;o>0;o>>=1) m=fmaxf(m,__shfl_down_sync(0xffffffffu,m,o));
    if((tid&31)==0) wmax[tid>>5]=m;
    __syncthreads();
    if(tid==0){
        float mm=wmax[0];
#pragma unroll
        for(int w=1;w<8;w++) mm=fmaxf(mm,wmax[w]);
        atomicMax(&g_maxbits[maxIdx],fenc(mm));
    }
}

__global__ void k_exp_scatter(const int* __restrict__ cl, int maxIdx){
    size_t i=(size_t)blockIdx.x*blockDim.x+threadIdx.x;
    if(i>=(size_t)NPTS*16) return;
    int n=(int)(i>>4); int c=((int)i&15)*4;
    float gmax=fdec(g_maxbits[maxIdx]);
    float4 v=*(float4*)(g_pw+(size_t)n*64+c);
    v.x=__expf(v.x-gmax); v.y=__expf(v.y-gmax); v.z=__expf(v.z-gmax); v.w=__expf(v.w-gmax);
    *(float4*)(g_pw+(size_t)n*64+c)=v;
    red4(g_segTmp+(size_t)cl[n]*64+c, v);
}

__global__ void k_pfeat_scatter(const int* __restrict__ cl, int ycol, int bnoff, size_t segOff){
    size_t i=(size_t)blockIdx.x*blockDim.x+threadIdx.x;
    if(i>=(size_t)NPTS*16) return;
    int n=(int)(i>>4); int c=((int)i&15)*4;
    float4 y=*(const float4*)(g_Y+(size_t)n*448+ycol+c);
    float4 sc=*(const float4*)(g_bnScale+bnoff+c);
    float4 sh=*(const float4*)(g_bnShift+bnoff+c);
    float4 o=bnrelu4(y,sc,sh);
    float4 e=*(const float4*)(g_pw+(size_t)n*64+c);
    int s=cl[n];
    float4 d=*(const float4*)(g_segTmp+(size_t)s*64+c);
    float4 val;
    val.x=o.x*e.x/(d.x+1e-6f); val.y=o.y*e.y/(d.y+1e-6f);
    val.z=o.z*e.z/(d.z+1e-6f); val.w=o.w*e.w/(d.w+1e-6f);
    red4(g_segP+segOff+(size_t)s*64+c, val);
}

__global__ void k_mix(const float* __restrict__ feat, const int* __restrict__ c0,
                      const int* __restrict__ c1, const int* __restrict__ c2,
                      const float* __restrict__ Wadp){
    __shared__ float ft[64*68];
    __shared__ float wa[192];
    __shared__ float adp[64*3];
    int r0=blockIdx.x*64, tid=threadIdx.x;
    int p=tid>>2, t4=tid&3, r=r0+p;
    if(tid<192) wa[tid]=Wadp[tid];
#pragma unroll
    for(int v=0;v<4;v++){
        int j=t4*16+v*4;
        float4 a=(r<NPTS)? *(const float4*)(feat+(size_t)r*64+j) : make_float4(0,0,0,0);
        *(float4*)(ft+p*68+j)=a;
    }
    __syncthreads();
    if(tid<64){
        float l0=0,l1=0,l2=0;
#pragma unroll 16
        for(int j=0;j<64;j++){
            float f=ft[tid*68+j];
            l0=fmaf(f,wa[j*3],l0); l1=fmaf(f,wa[j*3+1],l1); l2=fmaf(f,wa[j*3+2],l2);
        }
        float mx=fmaxf(l0,fmaxf(l1,l2));
        float e0=__expf(l0-mx), e1=__expf(l1-mx), e2=__expf(l2-mx);
        float inv=1.f/(e0+e1+e2);
        adp[tid*3]=e0*inv; adp[tid*3+1]=e1*inv; adp[tid*3+2]=e2*inv;
    }
    __syncthreads();
    if(r>=NPTS) return;
    float w0=adp[p*3], w1=adp[p*3+1], w2=adp[p*3+2];
    size_t b0=(size_t)c0[r]*64;
    size_t b1=(size_t)(SEG1+c1[r])*64;
    size_t b2=(size_t)(SEG2+c2[r])*64;
#pragma unroll
    for(int v=0;v<4;v++){
        int c=t4*16+v*4;
        float4 y=*(const float4*)(g_Y+(size_t)r*448+384+c);
        float4 sc=*(const float4*)(g_bnScale+384+c);
        float4 sh=*(const float4*)(g_bnShift+384+c);
        float4 fl=bnrelu4(y,sc,sh);
        float4 a0=*(const float4*)(g_segP+b0+c);
        float4 a1=*(const float4*)(g_segP+b1+c);
        float4 a2=*(const float4*)(g_segP+b2+c);
        float4 m;
        m.x=w0*a0.x+w1*a1.x+w2*a2.x; m.y=w0*a0.y+w1*a1.y+w2*a2.y;
        m.z=w0*a0.z+w1*a1.z+w2*a2.z; m.w=w0*a0.w+w1*a1.w+w2*a2.w;
        *(float4*)(g_cat+(size_t)r*128+c)=fl;
        *(float4*)(g_cat+(size_t)r*128+64+c)=m;
    }
}

__global__ void k_gemm128(const float* __restrict__ Wfuse){
    __shared__ float At[64*68];
    __shared__ float Bs[64*64];
    int r0=blockIdx.x*64, tid=threadIdx.x;
    int p=tid>>2, t4=tid&3, r=r0+p;
    int ty=tid>>4, tx=tid&15;
    ull acc[4][2]={};
    for(int kc=0;kc<2;kc++){
        __syncthreads();
#pragma unroll
        for(int v=0;v<4;v++){
            int j=t4*16+v*4;
            float4 a=(r<NPTS)? *(const float4*)(g_cat+(size_t)r*128+kc*64+j)
                             : make_float4(0,0,0,0);
            storeT(At,j,p,a);
        }
        for(int li=tid;li<1024;li+=256) ((float4*)Bs)[li]=((const float4*)(Wfuse+kc*4096))[li];
        __syncthreads();
#pragma unroll 16
        for(int j=0;j<64;j++){
            float4 a=*(float4*)(At+j*68+ty*4);
            ulonglong2 b=*(ulonglong2*)(Bs+j*64+tx*4);
            fma16p(acc,a,b);
        }
    }
    float s[4]={0,0,0,0}, q[4]={0,0,0,0};
#pragma unroll
    for(int u=0;u<4;u++){
        float4 o=row4(acc[u]);
        int rr=r0+ty*4+u;
        if(rr<NPTS)
            *(float4*)(g_z+(size_t)rr*64+tx*4)=o;
        s[0]+=o.x; q[0]+=o.x*o.x; s[1]+=o.y; q[1]+=o.y*o.y;
        s[2]+=o.z; q[2]+=o.z*o.z; s[3]+=o.w; q[3]+=o.w*o.w;
    }
    __syncthreads();
    float* redS=At; float* redQ=At+1024;
#pragma unroll
    for(int cu=0;cu<4;cu++){ redS[ty*64+tx*4+cu]=s[cu]; redQ[ty*64+tx*4+cu]=q[cu]; }
    __syncthreads();
    if(tid<64){
        float ss=0,qq=0;
#pragma unroll
        for(int y=0;y<16;y++){ ss+=redS[y*64+tid]; qq+=redQ[y*64+tid]; }
        atomicAdd(&g_colsum[448+tid],ss);
        atomicAdd(&g_colsq[448+tid],qq);
    }
}

__global__ void k_applyfuse(const float* __restrict__ feat){
    size_t i=(size_t)blockIdx.x*blockDim.x+threadIdx.x;
    if(i>=(size_t)NPTS*16) return;
    int n=(int)(i>>4); int c=((int)i&15)*4;
    float4 z=*(const float4*)(g_z+(size_t)n*64+c);
    float4 sc=*(const float4*)(g_bnScale+448+c);
    float4 sh=*(const float4*)(g_bnShift+448+c);
    float4 f=*(const float4*)(feat+(size_t)n*64+c);
    float4 o=bnrelu4(z,sc,sh);
    o.x+=f.x; o.y+=f.y; o.z+=f.z; o.w+=f.w;
    *(float4*)(g_fused+(size_t)n*64+c)=o;
}

// software-pipelined subm conv: prefetch k+1 gather under k's fma loop
__global__ void k_conv(int pass, const int* __restrict__ nbr, const float* __restrict__ W){
    __shared__ float At[64*68];
    __shared__ float Bs[64*64];
    __shared__ int nb[64*27];
    __shared__ float psc[64], psh[64];
    const float* fin = pass ? g_h1 : g_fused;
    float* outp = pass ? g_h2 : g_h1;
    int statsOff = pass ? 576 : 512;
    int r0=blockIdx.x*64, tid=threadIdx.x;
    for(int li=tid;li<1728;li+=256){
        size_t gi=(size_t)r0*27+li;
        nb[li]=(gi<(size_t)NPTS*27)? nbr[gi] : 0;
    }
    if(tid<64){
        psc[tid]=pass? g_bnScale[512+tid] : 1.f;
        psh[tid]=pass? g_bnShift[512+tid] : 0.f;
    }
    int ty=tid>>4, tx=tid&15, p=tid>>2, t4=tid&3, r=r0+p;
    __syncthreads();   // nb ready
    float4 pf[4];
    {
        const float* src=fin+(size_t)nb[p*27]*64;
#pragma unroll
        for(int v=0;v<4;v++){
            int j=t4*16+v*4;
            pf[v]=(r<NPTS)? *(const float4*)(src+j) : make_float4(0,0,0,0);
        }
    }
    ull acc[4][2]={};
    for(int k=0;k<27;k++){
        __syncthreads();   // At/Bs free
#pragma unroll
        for(int v=0;v<4;v++){
            int j=t4*16+v*4;
            float4 a=pf[v];
            if(pass){
                a.x=fmaxf(fmaf(a.x,psc[j],psh[j]),0.f);
                a.y=fmaxf(fmaf(a.y,psc[j+1],psh[j+1]),0.f);
                a.z=fmaxf(fmaf(a.z,psc[j+2],psh[j+2]),0.f);
                a.w=fmaxf(fmaf(a.w,psc[j+3],psh[j+3]),0.f);
            }
            storeT(At,j,p,a);
        }
        for(int li=tid;li<1024;li+=256)
            ((float4*)Bs)[li]=((const float4*)(W+k*4096))[li];
        if(k<26){   // prefetch next gather; retires under the fma loop
            const float* src=fin+(size_t)nb[p*27+k+1]*64;
#pragma unroll
            for(int v=0;v<4;v++){
                int j=t4*16+v*4;
                pf[v]=(r<NPTS)? *(const float4*)(src+j) : make_float4(0,0,0,0);
            }
        }
        __syncthreads();   // At/Bs ready
#pragma unroll 16
        for(int j=0;j<64;j++){
            float4 a=*(float4*)(At+j*68+ty*4);
            ulonglong2 b=*(ulonglong2*)(Bs+j*64+tx*4);
            fma16p(acc,a,b);
        }
    }
    float s[4]={0,0,0,0}, q[4]={0,0,0,0};
#pragma unroll
    for(int u=0;u<4;u++){
        float4 o=row4(acc[u]);
        int rr=r0+ty*4+u;
        if(rr<NPTS)
            *(float4*)(outp+(size_t)rr*64+tx*4)=o;
        s[0]+=o.x; q[0]+=o.x*o.x; s[1]+=o.y; q[1]+=o.y*o.y;
        s[2]+=o.z; q[2]+=o.z*o.z; s[3]+=o.w; q[3]+=o.w*o.w;
    }
    __syncthreads();
    float* redS=Bs; float* redQ=Bs+1024;
#pragma unroll
    for(int cu=0;cu<4;cu++){ redS[ty*64+tx*4+cu]=s[cu]; redQ[ty*64+tx*4+cu]=q[cu]; }
    __syncthreads();
    if(tid<64){
        float ss=0,qq=0;
#pragma unroll
        for(int y=0;y<16;y++){ ss+=redS[y*64+tid]; qq+=redQ[y*64+tid]; }
        atomicAdd(&g_colsum[statsOff+tid],ss);
        atomicAdd(&g_colsq[statsOff+tid],qq);
    }
}

__global__ void k_final(float* __restrict__ out){
    size_t i=(size_t)blockIdx.x*blockDim.x+threadIdx.x;
    if(i>=(size_t)NPTS*16) return;
    int n=(int)(i>>4); int c=((int)i&15)*4;
    float4 h=*(const float4*)(g_h2+(size_t)n*64+c);
    float4 sc=*(const float4*)(g_bnScale+576+c);
    float4 sh=*(const float4*)(g_bnShift+576+c);
    float4 f=*(const float4*)(g_fused+(size_t)n*64+c);
    float4 o;
    o.x=fmaxf(fmaf(h.x,sc.x,sh.x)+f.x,0.f);
    o.y=fmaxf(fmaf(h.y,sc.y,sh.y)+f.y,0.f);
    o.z=fmaxf(fmaf(h.z,sc.z,sh.z)+f.z,0.f);
    o.w=fmaxf(fmaf(h.w,sc.w,sh.w)+f.w,0.f);
    *(float4*)(out+(size_t)n*64+c)=o;
}

extern "C" void kernel_launch(void* const* d_in, const int* in_sizes, int n_in,
                              void* d_out, int out_size){
    const float* feat =(const float*)d_in[0];
    const int* c0=(const int*)d_in[1];
    const int* c1=(const int*)d_in[2];
    const int* c2=(const int*)d_in[3];
    const int* nbr=(const int*)d_in[4];
    const float* Wlw =(const float*)d_in[5];
    const float* glw =(const float*)d_in[6];
    const float* blw =(const float*)d_in[7];
    const float* Ww  =(const float*)d_in[8];
    const float* Wproj=(const float*)d_in[9];
    const float* gproj=(const float*)d_in[10];
    const float* bproj=(const float*)d_in[11];
    const float* Wadp=(const float*)d_in[12];
    const float* Wfuse=(const float*)d_in[13];
    const float* gfuse=(const float*)d_in[14];
    const float* bfuse=(const float*)d_in[15];
    const float* Wc1 =(const float*)d_in[16];
    const float* gc1 =(const float*)d_in[17];
    const float* bc1 =(const float*)d_in[18];
    const float* Wc2 =(const float*)d_in[19];
    const float* gc2 =(const float*)d_in[20];
    const float* bc2 =(const float*)d_in[21];
    float* out=(float*)d_out;

    k_zero_init<<<4096,256>>>();
    k_counts<<<(NPTS+255)/256,256>>>(c0,c1,c2);
    k_gemm_all<<<NT,256>>>(feat,Wlw,Wproj);
    k_bnparam448<<<2,256>>>(glw,blw,gproj,bproj);

    const int* cls[3]={c0,c1,c2};
    const int ncl[3]={NC0,NC1,NC2};
    const int cofs[3]={0,SEG1,SEG2};
    for(int i=0;i<3;i++){
        k_zero_segtmp<<<2048,256>>>((size_t)ncl[i]*64);
        k_pw_scatter<<<EWB,256>>>(cls[i], i*64, i*64);
        k_meansub_gemm<<<NT,256>>>(cls[i], Ww+i*4096, cofs[i], i);
        k_zero_segtmp<<<2048,256>>>((size_t)ncl[i]*64);
        k_exp_scatter<<<EWB,256>>>(cls[i], i);
        k_pfeat_scatter<<<EWB,256>>>(cls[i], 192+i*64, 192+i*64, (size_t)cofs[i]*64);
    }

    k_mix<<<NT,256>>>(feat,c0,c1,c2,Wadp);
    k_gemm128<<<NT,256>>>(Wfuse);
    k_bnparam64<<<1,64>>>(448,gfuse,bfuse);
    k_applyfuse<<<EWB,256>>>(feat);

    k_conv<<<NT,256>>>(0,nbr,Wc1);
    k_bnparam64<<<1,64>>>(512,gc1,bc1);
    k_conv<<<NT,256>>>(1,nbr,Wc2);
    k_bnparam64<<<1,64>>>(576,gc2,bc2);
    k_final<<<EWB,256>>>(out);
}

// round 15
// speedup vs baseline: 1.4802x; 1.4108x over previous
#include <cuda_runtime.h>
#include <cuda_bf16.h>
#include <cstdint>

#define NPTS 500000
#define NT 7813
#define EWB 31250
#define CB 3907
#define NC0 4096
#define NC1 32768
#define NC2 131072
#define SEG1 NC0
#define SEG2 (NC0+NC1)
#define SEGT (NC0+NC1+NC2)

#define SM_ALO 18432
#define SM_NB  36864
#define SMEMB  50688

__device__ __align__(16) float g_Y[(size_t)NPTS*448];
__device__ __align__(16) float g_pw[(size_t)NPTS*64];
__device__ __align__(16) float g_cat[(size_t)NPTS*128];
__device__ __align__(16) float g_z[(size_t)NPTS*64];
__device__ __align__(16) float g_fused[(size_t)NPTS*64];
__device__ __align__(16) float g_h1[(size_t)NPTS*64];
__device__ __align__(16) float g_h2[(size_t)NPTS*64];
__device__ __align__(16) __nv_bfloat16 g_bhi[(size_t)NPTS*64];
__device__ __align__(16) __nv_bfloat16 g_blo[(size_t)NPTS*64];
__device__ __align__(16) unsigned g_Wf[221184];   // [conv][half][27][4][8][32][2] u32
__device__ __align__(16) float g_segTmp[(size_t)NC2*64];
__device__ __align__(16) float g_segP[(size_t)SEGT*64];
__device__ float g_cnt[SEGT];
__device__ float g_colsum[640];
__device__ float g_colsq[640];
__device__ float g_bnScale[640];
__device__ float g_bnShift[640];
__device__ unsigned g_maxbits[3];

typedef unsigned long long ull;

__device__ __forceinline__ unsigned fenc(float f){
    unsigned u=__float_as_uint(f);
    return (u&0x80000000u)? ~u : (u|0x80000000u);
}
__device__ __forceinline__ float fdec(unsigned v){
    unsigned u=(v&0x80000000u)? (v^0x80000000u) : ~v;
    return __uint_as_float(u);
}
__device__ __forceinline__ void red4(float* addr, float4 v){
    asm volatile("red.global.add.v4.f32 [%0], {%1,%2,%3,%4};"
        :: "l"(addr), "f"(v.x), "f"(v.y), "f"(v.z), "f"(v.w) : "memory");
}
__device__ __forceinline__ ull dup2(float x){
    ull r; asm("mov.b64 %0, {%1, %1};" : "=l"(r) : "r"(__float_as_uint(x))); return r;
}
__device__ __forceinline__ void ffma2(ull &acc, ull a, ull b){
    asm("fma.rn.f32x2 %0, %1, %2, %3;" : "=l"(acc) : "l"(a), "l"(b), "l"(acc));
}
__device__ __forceinline__ float lo2(ull v){ return __uint_as_float((unsigned)v); }
__device__ __forceinline__ float hi2(ull v){ return __uint_as_float((unsigned)(v>>32)); }
__device__ __forceinline__ void fma16p(ull acc[4][2], float4 a, ulonglong2 b){
    ull a0=dup2(a.x), a1=dup2(a.y), a2=dup2(a.z), a3=dup2(a.w);
    ffma2(acc[0][0],a0,b.x); ffma2(acc[0][1],a0,b.y);
    ffma2(acc[1][0],a1,b.x); ffma2(acc[1][1],a1,b.y);
    ffma2(acc[2][0],a2,b.x); ffma2(acc[2][1],a2,b.y);
    ffma2(acc[3][0],a3,b.x); ffma2(acc[3][1],a3,b.y);
}
__device__ __forceinline__ float4 row4(ull* accu){
    return make_float4(lo2(accu[0]),hi2(accu[0]),lo2(accu[1]),hi2(accu[1]));
}
__device__ __forceinline__ float4 bnrelu4(float4 y, float4 sc, float4 sh){
    float4 o;
    o.x=fmaxf(fmaf(y.x,sc.x,sh.x),0.f); o.y=fmaxf(fmaf(y.y,sc.y,sh.y),0.f);
    o.z=fmaxf(fmaf(y.z,sc.z,sh.z),0.f); o.w=fmaxf(fmaf(y.w,sc.w,sh.w),0.f);
    return o;
}
__device__ __forceinline__ void storeT(float* At, int j, int p, float4 a){
    At[(j+0)*68+p]=a.x; At[(j+1)*68+p]=a.y; At[(j+2)*68+p]=a.z; At[(j+3)*68+p]=a.w;
}
__device__ __forceinline__ void split4(float4 v, size_t idx){
    __nv_bfloat162 h0=__floats2bfloat162_rn(v.x,v.y), h1=__floats2bfloat162_rn(v.z,v.w);
    float4 r;
    r.x=v.x-__low2float(h0); r.y=v.y-__high2float(h0);
    r.z=v.z-__low2float(h1); r.w=v.w-__high2float(h1);
    __nv_bfloat162 l0=__floats2bfloat162_rn(r.x,r.y), l1=__floats2bfloat162_rn(r.z,r.w);
    *(__nv_bfloat162*)(g_bhi+idx)=h0; *(__nv_bfloat162*)(g_bhi+idx+2)=h1;
    *(__nv_bfloat162*)(g_blo+idx)=l0; *(__nv_bfloat162*)(g_blo+idx+2)=l1;
}
__device__ __forceinline__ uint32_t smem_u32(const void* p){
    uint32_t a;
    asm("{ .reg .u64 t; cvta.to.shared.u64 t, %1; cvt.u32.u64 %0, t; }":"=r"(a):"l"(p));
    return a;
}
__device__ __forceinline__ void ldm4(uint32_t* a, uint32_t addr){
    asm volatile("ldmatrix.sync.aligned.m8n8.x4.shared.b16 {%0,%1,%2,%3},[%4];"
        : "=r"(a[0]),"=r"(a[1]),"=r"(a[2]),"=r"(a[3]) : "r"(addr));
}
__device__ __forceinline__ void mma16816(float* c, const uint32_t* a, uint32_t b0, uint32_t b1){
    asm volatile("mma.sync.aligned.m16n8k16.row.col.f32.bf16.bf16.f32 "
        "{%0,%1,%2,%3},{%4,%5,%6,%7},{%8,%9},{%0,%1,%2,%3};"
        : "+f"(c[0]),"+f"(c[1]),"+f"(c[2]),"+f"(c[3])
        : "r"(a[0]),"r"(a[1]),"r"(a[2]),"r"(a[3]),"r"(b0),"r"(b1));
}

__global__ void k_zero_init(){
    size_t i=(size_t)blockIdx.x*blockDim.x+threadIdx.x;
    size_t stride=(size_t)gridDim.x*blockDim.x;
    for(size_t j=i;j<(size_t)SEGT*64;j+=stride) g_segP[j]=0.f;
    if(i<SEGT) g_cnt[i]=0.f;
    if(i<640){ g_colsum[i]=0.f; g_colsq[i]=0.f; }
    if(i<3) g_maxbits[i]=0u;
}
__global__ void k_zero_segtmp(size_t n){
    size_t i=(size_t)blockIdx.x*blockDim.x+threadIdx.x;
    size_t stride=(size_t)gridDim.x*blockDim.x;
    for(size_t j=i;j<n;j+=stride) g_segTmp[j]=0.f;
}
__global__ void k_counts(const int* __restrict__ c0, const int* __restrict__ c1,
                         const int* __restrict__ c2){
    int n=blockIdx.x*blockDim.x+threadIdx.x;
    if(n<NPTS){
        atomicAdd(&g_cnt[c0[n]],1.f);
        atomicAdd(&g_cnt[SEG1+c1[n]],1.f);
        atomicAdd(&g_cnt[SEG2+c2[n]],1.f);
    }
}

__global__ void k_gemm_all(const float* __restrict__ feat, const float* __restrict__ Wlw,
                           const float* __restrict__ Wproj){
    __shared__ float At[64*68];
    __shared__ float Bs[64*64];
    __shared__ float redS[16*64];
    __shared__ float redQ[16*64];
    int r0=blockIdx.x*64, tid=threadIdx.x;
    int p=tid>>2, t4=tid&3, r=r0+p;
    int ty=tid>>4, tx=tid&15;
#pragma unroll
    for(int v=0;v<4;v++){
        int j=t4*16+v*4;
        float4 a=(r<NPTS)? *(const float4*)(feat+(size_t)r*64+j) : make_float4(0,0,0,0);
        storeT(At,j,p,a);
    }
    for(int t=0;t<7;t++){
        const float* W=(t<3)? (Wlw+t*4096) : (Wproj+(t-3)*4096);
        __syncthreads();
        for(int li=tid;li<1024;li+=256) ((float4*)Bs)[li]=((const float4*)W)[li];
        __syncthreads();
        ull acc[4][2]={};
#pragma unroll 16
        for(int j=0;j<64;j++){
            float4 a=*(float4*)(At+j*68+ty*4);
            ulonglong2 b=*(ulonglong2*)(Bs+j*64+tx*4);
            fma16p(acc,a,b);
        }
        float s[4]={0,0,0,0}, q[4]={0,0,0,0};
#pragma unroll
        for(int u=0;u<4;u++){
            float4 o=row4(acc[u]);
            int rr=r0+ty*4+u;
            if(rr<NPTS) *(float4*)(g_Y+(size_t)rr*448+t*64+tx*4)=o;
            s[0]+=o.x; q[0]+=o.x*o.x; s[1]+=o.y; q[1]+=o.y*o.y;
            s[2]+=o.z; q[2]+=o.z*o.z; s[3]+=o.w; q[3]+=o.w*o.w;
        }
#pragma unroll
        for(int cu=0;cu<4;cu++){ redS[ty*64+tx*4+cu]=s[cu]; redQ[ty*64+tx*4+cu]=q[cu]; }
        __syncthreads();
        if(tid<64){
            float ss=0,qq=0;
#pragma unroll
            for(int y=0;y<16;y++){ ss+=redS[y*64+tid]; qq+=redQ[y*64+tid]; }
            atomicAdd(&g_colsum[t*64+tid],ss);
            atomicAdd(&g_colsq[t*64+tid],qq);
        }
    }
}

__global__ void k_bnparam448(const float* __restrict__ glw, const float* __restrict__ blw,
                             const float* __restrict__ gproj, const float* __restrict__ bproj){
    int c=blockIdx.x*blockDim.x+threadIdx.x;
    if(c>=448) return;
    int grp=c>>6, ch=c&63;
    float g=(grp<3)? glw[grp*64+ch] : gproj[(grp-3)*64+ch];
    float b=(grp<3)? blw[grp*64+ch] : bproj[(grp-3)*64+ch];
    float inv=1.0f/(float)NPTS;
    float mu=g_colsum[c]*inv;
    float var=g_colsq[c]*inv-mu*mu;
    float sc=g*rsqrtf(var+1e-3f);
    g_bnScale[c]=sc; g_bnShift[c]=b-mu*sc;
}
__global__ void k_bnparam64(int off, const float* __restrict__ g, const float* __restrict__ b){
    int c=threadIdx.x;
    if(c>=64) return;
    float inv=1.0f/(float)NPTS;
    float mu=g_colsum[off+c]*inv;
    float var=g_colsq[off+c]*inv-mu*mu;
    float sc=g[c]*rsqrtf(var+1e-3f);
    g_bnScale[off+c]=sc; g_bnShift[off+c]=b[c]-mu*sc;
}

__global__ void k_pw_scatter(const int* __restrict__ cl, int ycol, int bnoff){
    size_t i=(size_t)blockIdx.x*blockDim.x+threadIdx.x;
    if(i>=(size_t)NPTS*16) return;
    int n=(int)(i>>4); int c=((int)i&15)*4;
    float4 y=*(const float4*)(g_Y+(size_t)n*448+ycol+c);
    float4 sc=*(const float4*)(g_bnScale+bnoff+c);
    float4 sh=*(const float4*)(g_bnShift+bnoff+c);
    float4 o=bnrelu4(y,sc,sh);
    *(float4*)(g_pw+(size_t)n*64+c)=o;
    red4(g_segTmp+(size_t)cl[n]*64+c, o);
}

__global__ void k_meansub_gemm(const int* __restrict__ cl, const float* __restrict__ Ww,
                               int cntOff, int maxIdx){
    __shared__ float At[64*68];
    __shared__ float Bs[64*64];
    __shared__ float wmax[8];
    int r0=blockIdx.x*64, tid=threadIdx.x;
    int p=tid>>2, t4=tid&3, r=r0+p;
    {
        int s=0; float inv=0.f;
        if(r<NPTS){ s=cl[r]; inv=1.f/fmaxf(g_cnt[cntOff+s],1.f); }
#pragma unroll
        for(int v=0;v<4;v++){
            int j=t4*16+v*4;
            float4 a=make_float4(0,0,0,0);
            if(r<NPTS){
                float4 pw=*(const float4*)(g_pw+(size_t)r*64+j);
                float4 m=*(const float4*)(g_segTmp+(size_t)s*64+j);
                a.x=pw.x-m.x*inv; a.y=pw.y-m.y*inv; a.z=pw.z-m.z*inv; a.w=pw.w-m.w*inv;
            }
            storeT(At,j,p,a);
        }
    }
    for(int li=tid;li<1024;li+=256) ((float4*)Bs)[li]=((const float4*)Ww)[li];
    __syncthreads();
    int ty=tid>>4, tx=tid&15;
    ull acc[4][2]={};
#pragma unroll 16
    for(int j=0;j<64;j++){
        float4 a=*(float4*)(At+j*68+ty*4);
        ulonglong2 b=*(ulonglong2*)(Bs+j*64+tx*4);
        fma16p(acc,a,b);
    }
    float m=-3.0e38f;
#pragma unroll
    for(int u=0;u<4;u++){
        int rr=r0+ty*4+u;
        if(rr<NPTS){
            float4 o=row4(acc[u]);
            *(float4*)(g_pw+(size_t)rr*64+tx*4)=o;
            m=fmaxf(m,fmaxf(fmaxf(o.x,o.y),fmaxf(o.z,o.w)));
        }
    }
#pragma unroll
    for(int o=16;o>0;o>>=1) m=fmaxf(m,__shfl_down_sync(0xffffffffu,m,o));
    if((tid&31)==0) wmax[tid>>5]=m;
    __syncthreads();
    if(tid==0){
        float mm=wmax[0];
#pragma unroll
        for(int w=1;w<8;w++) mm=fmaxf(mm,wmax[w]);
        atomicMax(&g_maxbits[maxIdx],fenc(mm));
    }
}

__global__ void k_exp_scatter(const int* __restrict__ cl, int maxIdx){
    size_t i=(size_t)blockIdx.x*blockDim.x+threadIdx.x;
    if(i>=(size_t)NPTS*16) return;
    int n=(int)(i>>4); int c=((int)i&15)*4;
    float gmax=fdec(g_maxbits[maxIdx]);
    float4 v=*(float4*)(g_pw+(size_t)n*64+c);
    v.x=__expf(v.x-gmax); v.y=__expf(v.y-gmax); v.z=__expf(v.z-gmax); v.w=__expf(v.w-gmax);
    *(float4*)(g_pw+(size_t)n*64+c)=v;
    red4(g_segTmp+(size_t)cl[n]*64+c, v);
}

__global__ void k_pfeat_scatter(const int* __restrict__ cl, int ycol, int bnoff, size_t segOff){
    size_t i=(size_t)blockIdx.x*blockDim.x+threadIdx.x;
    if(i>=(size_t)NPTS*16) return;
    int n=(int)(i>>4); int c=((int)i&15)*4;
    float4 y=*(const float4*)(g_Y+(size_t)n*448+ycol+c);
    float4 sc=*(const float4*)(g_bnScale+bnoff+c);
    float4 sh=*(const float4*)(g_bnShift+bnoff+c);
    float4 o=bnrelu4(y,sc,sh);
    float4 e=*(const float4*)(g_pw+(size_t)n*64+c);
    int s=cl[n];
    float4 d=*(const float4*)(g_segTmp+(size_t)s*64+c);
    float4 val;
    val.x=o.x*e.x/(d.x+1e-6f); val.y=o.y*e.y/(d.y+1e-6f);
    val.z=o.z*e.z/(d.z+1e-6f); val.w=o.w*e.w/(d.w+1e-6f);
    red4(g_segP+segOff+(size_t)s*64+c, val);
}

__global__ void k_mix(const float* __restrict__ feat, const int* __restrict__ c0,
                      const int* __restrict__ c1, const int* __restrict__ c2,
                      const float* __restrict__ Wadp){
    __shared__ float ft[64*68];
    __shared__ float wa[192];
    __shared__ float adp[64*3];
    int r0=blockIdx.x*64, tid=threadIdx.x;
    int p=tid>>2, t4=tid&3, r=r0+p;
    if(tid<192) wa[tid]=Wadp[tid];
#pragma unroll
    for(int v=0;v<4;v++){
        int j=t4*16+v*4;
        float4 a=(r<NPTS)? *(const float4*)(feat+(size_t)r*64+j) : make_float4(0,0,0,0);
        *(float4*)(ft+p*68+j)=a;
    }
    __syncthreads();
    if(tid<64){
        float l0=0,l1=0,l2=0;
#pragma unroll 16
        for(int j=0;j<64;j++){
            float f=ft[tid*68+j];
            l0=fmaf(f,wa[j*3],l0); l1=fmaf(f,wa[j*3+1],l1); l2=fmaf(f,wa[j*3+2],l2);
        }
        float mx=fmaxf(l0,fmaxf(l1,l2));
        float e0=__expf(l0-mx), e1=__expf(l1-mx), e2=__expf(l2-mx);
        float inv=1.f/(e0+e1+e2);
        adp[tid*3]=e0*inv; adp[tid*3+1]=e1*inv; adp[tid*3+2]=e2*inv;
    }
    __syncthreads();
    if(r>=NPTS) return;
    float w0=adp[p*3], w1=adp[p*3+1], w2=adp[p*3+2];
    size_t b0=(size_t)c0[r]*64;
    size_t b1=(size_t)(SEG1+c1[r])*64;
    size_t b2=(size_t)(SEG2+c2[r])*64;
#pragma unroll
    for(int v=0;v<4;v++){
        int c=t4*16+v*4;
        float4 y=*(const float4*)(g_Y+(size_t)r*448+384+c);
        float4 sc=*(const float4*)(g_bnScale+384+c);
        float4 sh=*(const float4*)(g_bnShift+384+c);
        float4 fl=bnrelu4(y,sc,sh);
        float4 a0=*(const float4*)(g_segP+b0+c);
        float4 a1=*(const float4*)(g_segP+b1+c);
        float4 a2=*(const float4*)(g_segP+b2+c);
        float4 m;
        m.x=w0*a0.x+w1*a1.x+w2*a2.x; m.y=w0*a0.y+w1*a1.y+w2*a2.y;
        m.z=w0*a0.z+w1*a1.z+w2*a2.z; m.w=w0*a0.w+w1*a1.w+w2*a2.w;
        *(float4*)(g_cat+(size_t)r*128+c)=fl;
        *(float4*)(g_cat+(size_t)r*128+64+c)=m;
    }
}

__global__ void k_gemm128(const float* __restrict__ Wfuse){
    __shared__ float At[64*68];
    __shared__ float Bs[64*64];
    int r0=blockIdx.x*64, tid=threadIdx.x;
    int p=tid>>2, t4=tid&3, r=r0+p;
    int ty=tid>>4, tx=tid&15;
    ull acc[4][2]={};
    for(int kc=0;kc<2;kc++){
        __syncthreads();
#pragma unroll
        for(int v=0;v<4;v++){
            int j=t4*16+v*4;
            float4 a=(r<NPTS)? *(const float4*)(g_cat+(size_t)r*128+kc*64+j)
                             : make_float4(0,0,0,0);
            storeT(At,j,p,a);
        }
        for(int li=tid;li<1024;li+=256) ((float4*)Bs)[li]=((const float4*)(Wfuse+kc*4096))[li];
        __syncthreads();
#pragma unroll 16
        for(int j=0;j<64;j++){
            float4 a=*(float4*)(At+j*68+ty*4);
            ulonglong2 b=*(ulonglong2*)(Bs+j*64+tx*4);
            fma16p(acc,a,b);
        }
    }
    float s[4]={0,0,0,0}, q[4]={0,0,0,0};
#pragma unroll
    for(int u=0;u<4;u++){
        float4 o=row4(acc[u]);
        int rr=r0+ty*4+u;
        if(rr<NPTS) *(float4*)(g_z+(size_t)rr*64+tx*4)=o;
        s[0]+=o.x; q[0]+=o.x*o.x; s[1]+=o.y; q[1]+=o.y*o.y;
        s[2]+=o.z; q[2]+=o.z*o.z; s[3]+=o.w; q[3]+=o.w*o.w;
    }
    __syncthreads();
    float* redS=At; float* redQ=At+1024;
#pragma unroll
    for(int cu=0;cu<4;cu++){ redS[ty*64+tx*4+cu]=s[cu]; redQ[ty*64+tx*4+cu]=q[cu]; }
    __syncthreads();
    if(tid<64){
        float ss=0,qq=0;
#pragma unroll
        for(int y=0;y<16;y++){ ss+=redS[y*64+tid]; qq+=redQ[y*64+tid]; }
        atomicAdd(&g_colsum[448+tid],ss);
        atomicAdd(&g_colsq[448+tid],qq);
    }
}

__global__ void k_applyfuse(const float* __restrict__ feat){
    size_t i=(size_t)blockIdx.x*blockDim.x+threadIdx.x;
    if(i>=(size_t)NPTS*16) return;
    int n=(int)(i>>4); int c=((int)i&15)*4;
    float4 z=*(const float4*)(g_z+(size_t)n*64+c);
    float4 sc=*(const float4*)(g_bnScale+448+c);
    float4 sh=*(const float4*)(g_bnShift+448+c);
    float4 f=*(const float4*)(feat+(size_t)n*64+c);
    float4 o=bnrelu4(z,sc,sh);
    o.x+=f.x; o.y+=f.y; o.z+=f.z; o.w+=f.w;
    *(float4*)(g_fused+(size_t)n*64+c)=o;
    split4(o,(size_t)n*64+c);
}

__global__ void k_split_h1(){
    size_t i=(size_t)blockIdx.x*blockDim.x+threadIdx.x;
    if(i>=(size_t)NPTS*16) return;
    int n=(int)(i>>4); int c=((int)i&15)*4;
    float4 v=*(const float4*)(g_h1+(size_t)n*64+c);
    float4 sc=*(const float4*)(g_bnScale+512+c);
    float4 sh=*(const float4*)(g_bnShift+512+c);
    v=bnrelu4(v,sc,sh);
    split4(v,(size_t)n*64+c);
}

// weights -> mma.sync B-fragment layout, hi/lo split
// g_Wf flat: [conv][half][k27][s4][t8][lane32][r2]
__global__ void k_makeWf(const float* __restrict__ W1, const float* __restrict__ W2){
    int i=blockIdx.x*blockDim.x+threadIdx.x;
    if(i>=221184) return;
    int r=i&1, lane=(i>>1)&31, t=(i>>6)&7, s=(i>>9)&3;
    int k=(i>>11)%27, rest=(i>>11)/27, half=rest&1, conv=rest>>1;
    int n=t*8+(lane>>2);
    int kk=s*16+(lane&3)*2+r*8;
    const float* W=conv? W2:W1;
    float w0=W[(k<<12)+(kk<<6)+n], w1=W[(k<<12)+((kk+1)<<6)+n];
    __nv_bfloat16 e0, e1;
    if(half==0){ e0=__float2bfloat16(w0); e1=__float2bfloat16(w1); }
    else{
        __nv_bfloat16 h0=__float2bfloat16(w0), h1=__float2bfloat16(w1);
        e0=__float2bfloat16(w0-__bfloat162float(h0));
        e1=__float2bfloat16(w1-__bfloat162float(h1));
    }
    unsigned v=((unsigned)*(unsigned short*)&e1<<16)|(unsigned)*(unsigned short*)&e0;
    g_Wf[i]=v;
}

// warp-level bf16 split-precision subm conv (mma.sync m16n8k16)
__global__ void __launch_bounds__(256,2) k_conv_mma(int pass, const int* __restrict__ nbr){
    extern __shared__ char sm[];
    float* outp = pass? g_h2 : g_h1;
    int r0=blockIdx.x*128, tid=threadIdx.x, wid=tid>>5, lane=tid&31;
    int* nb=(int*)(sm+SM_NB);
    for(int li=tid;li<128*27;li+=256){
        size_t gi=(size_t)r0*27+li;
        nb[li]=(gi<(size_t)NPTS*27)? nbr[gi]:0;
    }
    int row=tid>>1, half=tid&1;
    char* adst=sm+half*SM_ALO+row*144;
    // ldmatrix source address (per-lane) for this warp's 16-row slice
    uint32_t abase=smem_u32(sm)+ (wid*16+(lane&15))*144 + (lane>>4)*16;
    const unsigned* wf = g_Wf + (size_t)pass*110592;
    float acc[8][4]={};
    __syncthreads();
    for(int k=0;k<27;k++){
        const float4* src=(const float4*)((half? g_blo:g_bhi)+(size_t)nb[row*27+k]*64);
#pragma unroll
        for(int i=0;i<8;i++) *(float4*)(adst+i*16)=src[i];
        __syncthreads();
#pragma unroll
        for(int s=0;s<4;s++){
            uint32_t ah[4], al[4];
            ldm4(ah, abase+s*32);
            ldm4(al, abase+SM_ALO+s*32);
            const unsigned* fh=wf+((k*4+s)*8)*64+lane*2;
#pragma unroll
            for(int t=0;t<8;t++){
                ull bh=*(const ull*)(fh+t*64);
                ull bl=*(const ull*)(fh+55296+t*64);
                mma16816(acc[t], ah, (unsigned)bh, (unsigned)(bh>>32));
                mma16816(acc[t], ah, (unsigned)bl, (unsigned)(bl>>32));
                mma16816(acc[t], al, (unsigned)bh, (unsigned)(bh>>32));
            }
        }
        __syncthreads();
    }
    int m0=r0+wid*16+(lane>>2), m1=m0+8;
    int cb=(lane&3)*2;
#pragma unroll
    for(int t=0;t<8;t++){
        if(m0<NPTS) *(float2*)(outp+(size_t)m0*64+t*8+cb)=make_float2(acc[t][0],acc[t][1]);
        if(m1<NPTS) *(float2*)(outp+(size_t)m1*64+t*8+cb)=make_float2(acc[t][2],acc[t][3]);
    }
}

__global__ void k_colstats(int sel, int off){
    const float* buf = sel? g_h2 : g_h1;
    int tid=blockIdx.x*blockDim.x+threadIdx.x;
    int c=(tid&15)*4;
    float4 s=make_float4(0,0,0,0), q=make_float4(0,0,0,0);
    for(size_t n=(size_t)(tid>>4); n<NPTS; n+=4096){
        float4 v=*(const float4*)(buf+n*64+c);
        s.x+=v.x; q.x+=v.x*v.x; s.y+=v.y; q.y+=v.y*v.y;
        s.z+=v.z; q.z+=v.z*v.z; s.w+=v.w; q.w+=v.w*v.w;
    }
    red4(g_colsum+off+c, s);
    red4(g_colsq+off+c, q);
}

__global__ void k_final(float* __restrict__ out){
    size_t i=(size_t)blockIdx.x*blockDim.x+threadIdx.x;
    if(i>=(size_t)NPTS*16) return;
    int n=(int)(i>>4); int c=((int)i&15)*4;
    float4 h=*(const float4*)(g_h2+(size_t)n*64+c);
    float4 sc=*(const float4*)(g_bnScale+576+c);
    float4 sh=*(const float4*)(g_bnShift+576+c);
    float4 f=*(const float4*)(g_fused+(size_t)n*64+c);
    float4 o;
    o.x=fmaxf(fmaf(h.x,sc.x,sh.x)+f.x,0.f);
    o.y=fmaxf(fmaf(h.y,sc.y,sh.y)+f.y,0.f);
    o.z=fmaxf(fmaf(h.z,sc.z,sh.z)+f.z,0.f);
    o.w=fmaxf(fmaf(h.w,sc.w,sh.w)+f.w,0.f);
    *(float4*)(out+(size_t)n*64+c)=o;
}

extern "C" void kernel_launch(void* const* d_in, const int* in_sizes, int n_in,
                              void* d_out, int out_size){
    const float* feat =(const float*)d_in[0];
    const int* c0=(const int*)d_in[1];
    const int* c1=(const int*)d_in[2];
    const int* c2=(const int*)d_in[3];
    const int* nbr=(const int*)d_in[4];
    const float* Wlw =(const float*)d_in[5];
    const float* glw =(const float*)d_in[6];
    const float* blw =(const float*)d_in[7];
    const float* Ww  =(const float*)d_in[8];
    const float* Wproj=(const float*)d_in[9];
    const float* gproj=(const float*)d_in[10];
    const float* bproj=(const float*)d_in[11];
    const float* Wadp=(const float*)d_in[12];
    const float* Wfuse=(const float*)d_in[13];
    const float* gfuse=(const float*)d_in[14];
    const float* bfuse=(const float*)d_in[15];
    const float* Wc1 =(const float*)d_in[16];
    const float* gc1 =(const float*)d_in[17];
    const float* bc1 =(const float*)d_in[18];
    const float* Wc2 =(const float*)d_in[19];
    const float* gc2 =(const float*)d_in[20];
    const float* bc2 =(const float*)d_in[21];
    float* out=(float*)d_out;

    cudaFuncSetAttribute(k_conv_mma, cudaFuncAttributeMaxDynamicSharedMemorySize, SMEMB);

    k_zero_init<<<4096,256>>>();
    k_counts<<<(NPTS+255)/256,256>>>(c0,c1,c2);
    k_gemm_all<<<NT,256>>>(feat,Wlw,Wproj);
    k_bnparam448<<<2,256>>>(glw,blw,gproj,bproj);
    k_makeWf<<<864,256>>>(Wc1,Wc2);

    const int* cls[3]={c0,c1,c2};
    const int ncl[3]={NC0,NC1,NC2};
    const int cofs[3]={0,SEG1,SEG2};
    for(int i=0;i<3;i++){
        k_zero_segtmp<<<2048,256>>>((size_t)ncl[i]*64);
        k_pw_scatter<<<EWB,256>>>(cls[i], i*64, i*64);
        k_meansub_gemm<<<NT,256>>>(cls[i], Ww+i*4096, cofs[i], i);
        k_zero_segtmp<<<2048,256>>>((size_t)ncl[i]*64);
        k_exp_scatter<<<EWB,256>>>(cls[i], i);
        k_pfeat_scatter<<<EWB,256>>>(cls[i], 192+i*64, 192+i*64, (size_t)cofs[i]*64);
    }

    k_mix<<<NT,256>>>(feat,c0,c1,c2,Wadp);
    k_gemm128<<<NT,256>>>(Wfuse);
    k_bnparam64<<<1,64>>>(448,gfuse,bfuse);
    k_applyfuse<<<EWB,256>>>(feat);

    k_conv_mma<<<CB,256,SMEMB>>>(0,nbr);
    k_colstats<<<256,256>>>(0,512);
    k_bnparam64<<<1,64>>>(512,gc1,bc1);
    k_split_h1<<<EWB,256>>>();
    k_conv_mma<<<CB,256,SMEMB>>>(1,nbr);
    k_colstats<<<256,256>>>(1,576);
    k_bnparam64<<<1,64>>>(576,gc2,bc2);
    k_final<<<EWB,256>>>(out);
}